// round 3
// baseline (speedup 1.0000x reference)
#include <cuda_runtime.h>
#include <cstdint>
#include <math.h>

#define N_NODES 100000
#define N_EDGES 3200000
#define EPS_BN 1e-5f
#define EPS_NORM 1e-12f

// ---------------- device scratch (no allocation allowed) ----------------
__device__ __align__(16) float g_x0[N_NODES * 8];     // BN output (padded stride 8)
__device__ __align__(16) float g_x1[N_NODES * 64];    // conv1 output
__device__ __align__(16) float g_x2[N_NODES * 64];    // conv2 output
__device__ __align__(16) float g_y[N_NODES * 64];     // projected features (stride 64 or 8)
__device__ __align__(16) float g_agg[N_NODES * 64];   // conv2 accumulator
__device__ __align__(32) float g_agg8[N_NODES * 8];   // conv1/conv3 accumulator (5 feats + cnt)
__device__ float g_cinv[N_NODES];                     // 1/max(cnt,1)
__device__ float g_bnstats[16];                       // [0..4] sum, [5..9] sumsq
__device__ __align__(16) float2 g_csr[N_EDGES];       // packed (src_bits, weight) sorted by dst
__device__ int g_off[N_NODES + 1];                    // CSR row offsets
__device__ int g_degfill[2 * N_NODES];                // [0..N) degree, [N..2N) fill cursor

// ---------------- CSR build ----------------
__global__ void deg_hist_kernel(const int* __restrict__ dst, int* __restrict__ deg) {
    int e = blockIdx.x * blockDim.x + threadIdx.x;
    if (e < N_EDGES) atomicAdd(&deg[dst[e]], 1);
}

__global__ __launch_bounds__(1024) void scan_kernel(const int* __restrict__ deg,
                                                    int* __restrict__ off) {
    __shared__ int shw[32];
    int t = threadIdx.x;
    int lane = t & 31, wid = t >> 5;
    const int C = (N_NODES + 1023) / 1024;
    int b = t * C;
    int e = min(b + C, N_NODES);
    int s = 0;
    for (int i = b; i < e; i++) s += deg[i];
    // warp inclusive scan
    int incl = s;
#pragma unroll
    for (int k = 1; k < 32; k <<= 1) {
        int v = __shfl_up_sync(0xffffffffu, incl, k);
        if (lane >= k) incl += v;
    }
    if (lane == 31) shw[wid] = incl;
    __syncthreads();
    if (wid == 0) {
        int ws = shw[lane];
        int wi = ws;
#pragma unroll
        for (int k = 1; k < 32; k <<= 1) {
            int v = __shfl_up_sync(0xffffffffu, wi, k);
            if (lane >= k) wi += v;
        }
        shw[lane] = wi - ws;  // exclusive base per warp
    }
    __syncthreads();
    int base = shw[wid] + incl - s;  // exclusive prefix for this thread
    for (int i = b; i < e; i++) {
        off[i] = base;
        base += deg[i];
    }
    if (t == 1023) off[N_NODES] = N_EDGES;
}

__global__ void fill_kernel(const int* __restrict__ src,
                            const int* __restrict__ dst,
                            const float* __restrict__ ew,
                            const int* __restrict__ off,
                            int* __restrict__ fill,
                            float2* __restrict__ csr) {
    int e = blockIdx.x * blockDim.x + threadIdx.x;
    if (e >= N_EDGES) return;
    int d = dst[e];
    int pos = off[d] + atomicAdd(&fill[d], 1);
    csr[pos] = make_float2(__int_as_float(src[e]), ew[e]);
}

// ---------------- BatchNorm statistics ----------------
__global__ void bn_stats_kernel(const float* __restrict__ h) {
    float s[5] = {0, 0, 0, 0, 0}, q[5] = {0, 0, 0, 0, 0};
    int stride = gridDim.x * blockDim.x;
    for (int n = blockIdx.x * blockDim.x + threadIdx.x; n < N_NODES; n += stride) {
#pragma unroll
        for (int i = 0; i < 5; i++) {
            float v = h[n * 5 + i];
            s[i] += v;
            q[i] += v * v;
        }
    }
#pragma unroll
    for (int k = 16; k > 0; k >>= 1) {
#pragma unroll
        for (int i = 0; i < 5; i++) {
            s[i] += __shfl_down_sync(0xffffffffu, s[i], k);
            q[i] += __shfl_down_sync(0xffffffffu, q[i], k);
        }
    }
    __shared__ float sh[10];
    if (threadIdx.x < 10) sh[threadIdx.x] = 0.f;
    __syncthreads();
    if ((threadIdx.x & 31) == 0) {
#pragma unroll
        for (int i = 0; i < 5; i++) {
            atomicAdd(&sh[i], s[i]);
            atomicAdd(&sh[5 + i], q[i]);
        }
    }
    __syncthreads();
    if (threadIdx.x < 10) atomicAdd(&g_bnstats[threadIdx.x], sh[threadIdx.x]);
}

// ------- BN apply + conv1 projection (5x5) -> y8 -------
__global__ void bn_conv1_kernel(const float* __restrict__ h,
                                const float* __restrict__ gamma,
                                const float* __restrict__ beta,
                                const float* __restrict__ pw,
                                const float* __restrict__ pb,
                                float* __restrict__ x0p,
                                float* __restrict__ y8) {
    int n = blockIdx.x * blockDim.x + threadIdx.x;
    if (n >= N_NODES) return;
    const float inv_n = 1.f / (float)N_NODES;
    float xr[5];
#pragma unroll
    for (int i = 0; i < 5; i++) {
        float mu = g_bnstats[i] * inv_n;
        float var = g_bnstats[5 + i] * inv_n - mu * mu;
        float sc = rsqrtf(var + EPS_BN) * gamma[i];
        xr[i] = (h[n * 5 + i] - mu) * sc + beta[i];
    }
    float4* x0v = reinterpret_cast<float4*>(x0p + (size_t)n * 8);
    x0v[0] = make_float4(xr[0], xr[1], xr[2], xr[3]);
    x0v[1] = make_float4(xr[4], 0.f, 0.f, 0.f);
    float xp[5];
#pragma unroll
    for (int k = 0; k < 5; k++) {
        float v = pb[k];
#pragma unroll
        for (int i = 0; i < 5; i++) v += xr[i] * pw[i * 5 + k];
        xp[k] = fmaxf(v, 0.f);
    }
    float4* yv = reinterpret_cast<float4*>(y8 + (size_t)n * 8);
    yv[0] = make_float4(xp[0], xp[1], xp[2], xp[3]);
    yv[1] = make_float4(xp[4], 0.f, 0.f, 0.f);
}

// ---------------- width-8 pull gather: warp per node ----------------
__global__ void gather8_kernel(const int* __restrict__ off,
                               const float2* __restrict__ csr,
                               const float* __restrict__ y8,
                               float* __restrict__ agg8) {
    int gw = (blockIdx.x * blockDim.x + threadIdx.x) >> 5;
    if (gw >= N_NODES) return;
    int lane = threadIdx.x & 31;
    int beg = off[gw], end = off[gw + 1];
    float a0 = 0.f, a1 = 0.f, a2 = 0.f, a3 = 0.f, a4 = 0.f;
    for (int j = beg + lane; j < end; j += 32) {
        float2 rec = csr[j];
        int s = __float_as_int(rec.x);
        float w = rec.y;
        const float4* yv = reinterpret_cast<const float4*>(y8 + (size_t)s * 8);
        float4 va = yv[0];
        float v4 = y8[(size_t)s * 8 + 4];
        a0 += va.x * w;
        a1 += va.y * w;
        a2 += va.z * w;
        a3 += va.w * w;
        a4 += v4 * w;
    }
#pragma unroll
    for (int k = 16; k > 0; k >>= 1) {
        a0 += __shfl_xor_sync(0xffffffffu, a0, k);
        a1 += __shfl_xor_sync(0xffffffffu, a1, k);
        a2 += __shfl_xor_sync(0xffffffffu, a2, k);
        a3 += __shfl_xor_sync(0xffffffffu, a3, k);
        a4 += __shfl_xor_sync(0xffffffffu, a4, k);
    }
    if (lane == 0) {
        float4* av = reinterpret_cast<float4*>(agg8 + (size_t)gw * 8);
        av[0] = make_float4(a0, a1, a2, a3);
        av[1] = make_float4(a4, (float)(end - beg), 0.f, 0.f);
    }
}

// ---------------- width-64 pull gather: warp per node, 2 edge-halves ----------------
__global__ void gather64_kernel(const int* __restrict__ off,
                                const float2* __restrict__ csr,
                                const float* __restrict__ y,
                                float* __restrict__ agg) {
    int gw = (blockIdx.x * blockDim.x + threadIdx.x) >> 5;
    if (gw >= N_NODES) return;
    int lane = threadIdx.x & 31;
    int half = lane >> 4;
    int f = (lane & 15) << 2;
    int beg = off[gw], end = off[gw + 1];
    float4 acc = make_float4(0.f, 0.f, 0.f, 0.f);
    for (int j = beg + half; j < end; j += 2) {
        float2 rec = csr[j];
        int s = __float_as_int(rec.x);
        float w = rec.y;
        float4 v = *reinterpret_cast<const float4*>(y + (size_t)s * 64 + f);
        acc.x += v.x * w;
        acc.y += v.y * w;
        acc.z += v.z * w;
        acc.w += v.w * w;
    }
    acc.x += __shfl_xor_sync(0xffffffffu, acc.x, 16);
    acc.y += __shfl_xor_sync(0xffffffffu, acc.y, 16);
    acc.z += __shfl_xor_sync(0xffffffffu, acc.z, 16);
    acc.w += __shfl_xor_sync(0xffffffffu, acc.w, 16);
    if (half == 0)
        *reinterpret_cast<float4*>(agg + (size_t)gw * 64 + f) = acc;
}

// ------- conv1 finalize: out64 = mean5@lw + lb + x0@rw ; norm ; relu -------
// two-pass (ss, then recompute+store) to keep register count low
__global__ __launch_bounds__(128) void fin1_kernel(const float* __restrict__ x0p,
                                                   const float* __restrict__ agg8,
                                                   const float* __restrict__ lw,
                                                   const float* __restrict__ lb,
                                                   const float* __restrict__ rw,
                                                   float* __restrict__ x1,
                                                   float* __restrict__ cinv_out) {
    __shared__ float4 s_lw[80], s_rw[80], s_lb[16];
    int t = threadIdx.x;
    if (t < 80) {
        s_lw[t] = reinterpret_cast<const float4*>(lw)[t];
        s_rw[t] = reinterpret_cast<const float4*>(rw)[t];
    }
    if (t < 16) s_lb[t] = reinterpret_cast<const float4*>(lb)[t];
    __syncthreads();
    int n = blockIdx.x * 128 + t;
    if (n >= N_NODES) return;

    const float4* av = reinterpret_cast<const float4*>(agg8 + (size_t)n * 8);
    float4 a0 = av[0], a1 = av[1];
    float ci = 1.f / fmaxf(a1.y, 1.f);
    cinv_out[n] = ci;
    float m[5] = {a0.x * ci, a0.y * ci, a0.z * ci, a0.w * ci, a1.x * ci};
    const float4* xv = reinterpret_cast<const float4*>(x0p + (size_t)n * 8);
    float4 x0a = xv[0], x0b = xv[1];
    float xr[5] = {x0a.x, x0a.y, x0a.z, x0a.w, x0b.x};

    float ss = 0.f;
#pragma unroll
    for (int oq = 0; oq < 16; oq++) {
        float4 v = s_lb[oq];
#pragma unroll
        for (int i = 0; i < 5; i++) {
            float4 w1 = s_lw[i * 16 + oq];
            float4 w2 = s_rw[i * 16 + oq];
            v.x += m[i] * w1.x + xr[i] * w2.x;
            v.y += m[i] * w1.y + xr[i] * w2.y;
            v.z += m[i] * w1.z + xr[i] * w2.z;
            v.w += m[i] * w1.w + xr[i] * w2.w;
        }
        ss += v.x * v.x + v.y * v.y + v.z * v.z + v.w * v.w;
    }
    float sc = 1.f / fmaxf(sqrtf(ss), EPS_NORM);
    float4* xo = reinterpret_cast<float4*>(x1 + (size_t)n * 64);
#pragma unroll
    for (int oq = 0; oq < 16; oq++) {
        float4 v = s_lb[oq];
#pragma unroll
        for (int i = 0; i < 5; i++) {
            float4 w1 = s_lw[i * 16 + oq];
            float4 w2 = s_rw[i * 16 + oq];
            v.x += m[i] * w1.x + xr[i] * w2.x;
            v.y += m[i] * w1.y + xr[i] * w2.y;
            v.z += m[i] * w1.z + xr[i] * w2.z;
            v.w += m[i] * w1.w + xr[i] * w2.w;
        }
        xo[oq] = make_float4(fmaxf(v.x * sc, 0.f), fmaxf(v.y * sc, 0.f),
                             fmaxf(v.z * sc, 0.f), fmaxf(v.w * sc, 0.f));
    }
}

// ---------------- y = relu(x@pw + pb) @ lw  (64 -> 64 -> OUT2) ----------------
template <int OUT2>
__global__ __launch_bounds__(128) void proj_lw_kernel(const float* __restrict__ x,
                                                      const float* __restrict__ pw,
                                                      const float* __restrict__ pb,
                                                      const float* __restrict__ lw,
                                                      float* __restrict__ y) {
    constexpr int OUTP = (OUT2 == 64) ? 64 : 8;
    constexpr int YS = (OUT2 == 64) ? 64 : 8;
    constexpr int NPB = 32;
    constexpr int XS = 36;
    __shared__ float s_w[64 * 64];
    __shared__ float s_x[64 * XS];
    __shared__ float s_xp[64 * XS];
    __shared__ float s_pb[64];
    const int t = threadIdx.x;
    const int n0 = blockIdx.x * NPB;

    for (int i4 = t; i4 < 1024; i4 += 128)
        reinterpret_cast<float4*>(s_w)[i4] = reinterpret_cast<const float4*>(pw)[i4];
    if (t < 64) s_pb[t] = pb[t];
    for (int idx = t; idx < NPB * 64; idx += 128) {
        int n = idx >> 6, i = idx & 63;
        s_x[i * XS + n] = x[(size_t)(n0 + n) * 64 + i];
    }
    __syncthreads();

    const int oq = t & 15, nq = t >> 4;
    float acc[4][4];
#pragma unroll
    for (int a = 0; a < 4; a++)
#pragma unroll
        for (int b = 0; b < 4; b++) acc[a][b] = 0.f;

#pragma unroll 8
    for (int i = 0; i < 64; i++) {
        float4 xv = *reinterpret_cast<const float4*>(&s_x[i * XS + (nq << 2)]);
        float4 wv = *reinterpret_cast<const float4*>(&s_w[(i << 6) + (oq << 2)]);
        acc[0][0] += xv.x * wv.x; acc[0][1] += xv.x * wv.y; acc[0][2] += xv.x * wv.z; acc[0][3] += xv.x * wv.w;
        acc[1][0] += xv.y * wv.x; acc[1][1] += xv.y * wv.y; acc[1][2] += xv.y * wv.z; acc[1][3] += xv.y * wv.w;
        acc[2][0] += xv.z * wv.x; acc[2][1] += xv.z * wv.y; acc[2][2] += xv.z * wv.z; acc[2][3] += xv.z * wv.w;
        acc[3][0] += xv.w * wv.x; acc[3][1] += xv.w * wv.y; acc[3][2] += xv.w * wv.z; acc[3][3] += xv.w * wv.w;
    }
#pragma unroll
    for (int dk = 0; dk < 4; dk++) {
        float b = s_pb[(oq << 2) + dk];
#pragma unroll
        for (int dn = 0; dn < 4; dn++) {
            s_xp[((oq << 2) + dk) * XS + (nq << 2) + dn] = fmaxf(acc[dn][dk] + b, 0.f);
        }
    }
    __syncthreads();

    if (OUT2 == 64) {
        for (int i4 = t; i4 < 1024; i4 += 128)
            reinterpret_cast<float4*>(s_w)[i4] = reinterpret_cast<const float4*>(lw)[i4];
    } else {
        for (int idx = t; idx < 64 * 8; idx += 128) s_w[idx] = 0.f;
        __syncthreads();
        for (int idx = t; idx < 64 * 5; idx += 128) s_w[(idx / 5) * 8 + (idx % 5)] = lw[idx];
    }
    __syncthreads();

    constexpr int OQ2 = OUTP / 4;
    if (oq < OQ2) {
        float a2[4][4];
#pragma unroll
        for (int a = 0; a < 4; a++)
#pragma unroll
            for (int b = 0; b < 4; b++) a2[a][b] = 0.f;
#pragma unroll 8
        for (int i = 0; i < 64; i++) {
            float4 xv = *reinterpret_cast<const float4*>(&s_xp[i * XS + (nq << 2)]);
            float4 wv = *reinterpret_cast<const float4*>(&s_w[i * OUTP + (oq << 2)]);
            a2[0][0] += xv.x * wv.x; a2[0][1] += xv.x * wv.y; a2[0][2] += xv.x * wv.z; a2[0][3] += xv.x * wv.w;
            a2[1][0] += xv.y * wv.x; a2[1][1] += xv.y * wv.y; a2[1][2] += xv.y * wv.z; a2[1][3] += xv.y * wv.w;
            a2[2][0] += xv.z * wv.x; a2[2][1] += xv.z * wv.y; a2[2][2] += xv.z * wv.z; a2[2][3] += xv.z * wv.w;
            a2[3][0] += xv.w * wv.x; a2[3][1] += xv.w * wv.y; a2[3][2] += xv.w * wv.z; a2[3][3] += xv.w * wv.w;
        }
#pragma unroll
        for (int dn = 0; dn < 4; dn++) {
            float4 o4 = make_float4(a2[dn][0], a2[dn][1], a2[dn][2], a2[dn][3]);
            *reinterpret_cast<float4*>(&y[(size_t)(n0 + (nq << 2) + dn) * YS + (oq << 2)]) = o4;
        }
    }
}

// ------- conv2 finalize: out = agg*cinv + lb + x@rw ; norm ; relu -------
__global__ __launch_bounds__(128) void fin64_kernel(const float* __restrict__ x,
                                                    const float* __restrict__ agg,
                                                    const float* __restrict__ cinv,
                                                    const float* __restrict__ rw,
                                                    const float* __restrict__ lb,
                                                    float* __restrict__ out) {
    constexpr int NPB = 32;
    constexpr int XS = 36;
    __shared__ float s_w[64 * 64];
    __shared__ float s_x[64 * XS];
    __shared__ float s_lb[64];
    const int t = threadIdx.x;
    const int n0 = blockIdx.x * NPB;

    for (int i4 = t; i4 < 1024; i4 += 128)
        reinterpret_cast<float4*>(s_w)[i4] = reinterpret_cast<const float4*>(rw)[i4];
    if (t < 64) s_lb[t] = lb[t];
    for (int idx = t; idx < NPB * 64; idx += 128) {
        int n = idx >> 6, i = idx & 63;
        s_x[i * XS + n] = x[(size_t)(n0 + n) * 64 + i];
    }
    __syncthreads();

    const int oq = t & 15, nq = t >> 4;
    float acc[4][4];
#pragma unroll
    for (int a = 0; a < 4; a++)
#pragma unroll
        for (int b = 0; b < 4; b++) acc[a][b] = 0.f;
#pragma unroll 8
    for (int i = 0; i < 64; i++) {
        float4 xv = *reinterpret_cast<const float4*>(&s_x[i * XS + (nq << 2)]);
        float4 wv = *reinterpret_cast<const float4*>(&s_w[(i << 6) + (oq << 2)]);
        acc[0][0] += xv.x * wv.x; acc[0][1] += xv.x * wv.y; acc[0][2] += xv.x * wv.z; acc[0][3] += xv.x * wv.w;
        acc[1][0] += xv.y * wv.x; acc[1][1] += xv.y * wv.y; acc[1][2] += xv.y * wv.z; acc[1][3] += xv.y * wv.w;
        acc[2][0] += xv.z * wv.x; acc[2][1] += xv.z * wv.y; acc[2][2] += xv.z * wv.z; acc[2][3] += xv.z * wv.w;
        acc[3][0] += xv.w * wv.x; acc[3][1] += xv.w * wv.y; acc[3][2] += xv.w * wv.z; acc[3][3] += xv.w * wv.w;
    }

    float lb0 = s_lb[(oq << 2) + 0], lb1 = s_lb[(oq << 2) + 1];
    float lb2 = s_lb[(oq << 2) + 2], lb3 = s_lb[(oq << 2) + 3];
#pragma unroll
    for (int dn = 0; dn < 4; dn++) {
        int n = n0 + (nq << 2) + dn;
        float ci = cinv[n];
        float4 ag = *reinterpret_cast<const float4*>(&agg[(size_t)n * 64 + (oq << 2)]);
        float v0 = acc[dn][0] + lb0 + ag.x * ci;
        float v1 = acc[dn][1] + lb1 + ag.y * ci;
        float v2 = acc[dn][2] + lb2 + ag.z * ci;
        float v3 = acc[dn][3] + lb3 + ag.w * ci;
        float ss = v0 * v0 + v1 * v1 + v2 * v2 + v3 * v3;
        ss += __shfl_down_sync(0xffffffffu, ss, 8, 16);
        ss += __shfl_down_sync(0xffffffffu, ss, 4, 16);
        ss += __shfl_down_sync(0xffffffffu, ss, 2, 16);
        ss += __shfl_down_sync(0xffffffffu, ss, 1, 16);
        ss = __shfl_sync(0xffffffffu, ss, 0, 16);
        float sc = 1.f / fmaxf(sqrtf(ss), EPS_NORM);
        float4 o4 = make_float4(fmaxf(v0 * sc, 0.f), fmaxf(v1 * sc, 0.f),
                                fmaxf(v2 * sc, 0.f), fmaxf(v3 * sc, 0.f));
        *reinterpret_cast<float4*>(&out[(size_t)n * 64 + (oq << 2)]) = o4;
    }
}

// ------- conv3 finalize: out5 = agg*cinv + lb + x2@rw ; norm (no relu) -------
__global__ __launch_bounds__(128) void fin3_kernel(const float* __restrict__ x2,
                                                   const float* __restrict__ agg8,
                                                   const float* __restrict__ cinv,
                                                   const float* __restrict__ rw,
                                                   const float* __restrict__ lb,
                                                   float* __restrict__ out) {
    __shared__ float s_rw[64 * 8];
    __shared__ float s_lb[8];
    int t = threadIdx.x;
    for (int idx = t; idx < 320; idx += 128) s_rw[(idx / 5) * 8 + (idx % 5)] = rw[idx];
    if (t < 5) s_lb[t] = lb[t];
    __syncthreads();
    int n = blockIdx.x * 128 + t;
    if (n >= N_NODES) return;

    float ci = cinv[n];
    const float4* av = reinterpret_cast<const float4*>(agg8 + (size_t)n * 8);
    float4 a0 = av[0], a1 = av[1];
    float4 vf = make_float4(s_lb[0] + a0.x * ci, s_lb[1] + a0.y * ci,
                            s_lb[2] + a0.z * ci, s_lb[3] + a0.w * ci);
    float v4 = s_lb[4] + a1.x * ci;

    const float4* xr = reinterpret_cast<const float4*>(x2 + (size_t)n * 64);
#pragma unroll
    for (int iq = 0; iq < 16; iq++) {
        float4 xv = xr[iq];
        float xs[4] = {xv.x, xv.y, xv.z, xv.w};
#pragma unroll
        for (int c = 0; c < 4; c++) {
            int i = iq * 4 + c;
            float4 w = *reinterpret_cast<const float4*>(&s_rw[i * 8]);
            float w4 = s_rw[i * 8 + 4];
            vf.x += xs[c] * w.x;
            vf.y += xs[c] * w.y;
            vf.z += xs[c] * w.z;
            vf.w += xs[c] * w.w;
            v4 += xs[c] * w4;
        }
    }
    float ss = vf.x * vf.x + vf.y * vf.y + vf.z * vf.z + vf.w * vf.w + v4 * v4;
    float sc = 1.f / fmaxf(sqrtf(ss), EPS_NORM);
    float* o = out + (size_t)n * 5;
    o[0] = vf.x * sc;
    o[1] = vf.y * sc;
    o[2] = vf.z * sc;
    o[3] = vf.w * sc;
    o[4] = v4 * sc;
}

// ---------------- host launcher ----------------
extern "C" void kernel_launch(void* const* d_in, const int* in_sizes, int n_in,
                              void* d_out, int out_size) {
    const float* h = (const float*)d_in[0];
    const int* ei = (const int*)d_in[1];
    const float* ew = (const float*)d_in[2];
    const float* gamma = (const float*)d_in[3];
    const float* beta = (const float*)d_in[4];
    const float* c1_pw = (const float*)d_in[5];
    const float* c1_pb = (const float*)d_in[6];
    const float* c1_lw = (const float*)d_in[7];
    const float* c1_lb = (const float*)d_in[8];
    const float* c1_rw = (const float*)d_in[9];
    const float* c2_pw = (const float*)d_in[10];
    const float* c2_pb = (const float*)d_in[11];
    const float* c2_lw = (const float*)d_in[12];
    const float* c2_lb = (const float*)d_in[13];
    const float* c2_rw = (const float*)d_in[14];
    const float* c3_pw = (const float*)d_in[15];
    const float* c3_pb = (const float*)d_in[16];
    const float* c3_lw = (const float*)d_in[17];
    const float* c3_lb = (const float*)d_in[18];
    const float* c3_rw = (const float*)d_in[19];
    float* out = (float*)d_out;

    const int* src = ei;
    const int* dst = ei + N_EDGES;

    float *x0, *x1, *x2, *y, *agg, *agg8, *cinv, *stats;
    float2* csr;
    int *off, *degfill;
    cudaGetSymbolAddress((void**)&x0, g_x0);
    cudaGetSymbolAddress((void**)&x1, g_x1);
    cudaGetSymbolAddress((void**)&x2, g_x2);
    cudaGetSymbolAddress((void**)&y, g_y);
    cudaGetSymbolAddress((void**)&agg, g_agg);
    cudaGetSymbolAddress((void**)&agg8, g_agg8);
    cudaGetSymbolAddress((void**)&cinv, g_cinv);
    cudaGetSymbolAddress((void**)&stats, g_bnstats);
    cudaGetSymbolAddress((void**)&csr, g_csr);
    cudaGetSymbolAddress((void**)&off, g_off);
    cudaGetSymbolAddress((void**)&degfill, g_degfill);

    int* deg = degfill;
    int* fill = degfill + N_NODES;

    cudaMemsetAsync(stats, 0, sizeof(float) * 16, 0);
    cudaMemsetAsync(degfill, 0, sizeof(int) * 2 * N_NODES, 0);

    // CSR build
    deg_hist_kernel<<<(N_EDGES + 255) / 256, 256>>>(dst, deg);
    scan_kernel<<<1, 1024>>>(deg, off);
    fill_kernel<<<(N_EDGES + 255) / 256, 256>>>(src, dst, ew, off, fill, csr);

    // BatchNorm + conv1 projection
    bn_stats_kernel<<<128, 256>>>(h);
    bn_conv1_kernel<<<(N_NODES + 255) / 256, 256>>>(h, gamma, beta, c1_pw, c1_pb, x0, y);

    // conv1: pull-gather (width 5) + finalize
    gather8_kernel<<<(N_NODES * 32 + 255) / 256, 256>>>(off, csr, y, agg8);
    fin1_kernel<<<(N_NODES + 127) / 128, 128>>>(x0, agg8, c1_lw, c1_lb, c1_rw, x1, cinv);

    // conv2
    proj_lw_kernel<64><<<N_NODES / 32, 128>>>(x1, c2_pw, c2_pb, c2_lw, y);
    gather64_kernel<<<(N_NODES * 32 + 255) / 256, 256>>>(off, csr, y, agg);
    fin64_kernel<<<N_NODES / 32, 128>>>(x1, agg, cinv, c2_rw, c2_lb, x2);

    // conv3
    proj_lw_kernel<5><<<N_NODES / 32, 128>>>(x2, c3_pw, c3_pb, c3_lw, y);
    gather8_kernel<<<(N_NODES * 32 + 255) / 256, 256>>>(off, csr, y, agg8);
    fin3_kernel<<<(N_NODES + 127) / 128, 128>>>(x2, agg8, cinv, c3_rw, c3_lb, out);
}

// round 4
// speedup vs baseline: 1.0219x; 1.0219x over previous
#include <cuda_runtime.h>
#include <cuda_fp16.h>
#include <cstdint>
#include <math.h>

#define N_NODES 100000
#define N_EDGES 3200000
#define EPS_BN 1e-5f
#define EPS_NORM 1e-12f

// ---------------- device scratch (no allocation allowed) ----------------
__device__ __align__(16) float g_x0[N_NODES * 8];     // BN output (padded stride 8)
__device__ __align__(16) float g_x1[N_NODES * 64];    // conv1 output
__device__ __align__(16) float g_x2[N_NODES * 64];    // conv2 output
__device__ __align__(16) __half g_yh[N_NODES * 64];   // fp16 projected features (stride 64 or 8)
__device__ __align__(16) float g_agg[N_NODES * 64];   // conv2 accumulator
__device__ __align__(32) float g_agg8[N_NODES * 8];   // conv1/conv3 accumulator (5 feats + cnt)
__device__ float g_cinv[N_NODES];                     // 1/max(cnt,1)
__device__ float g_bnstats[16];                       // [0..4] sum, [5..9] sumsq
__device__ __align__(16) float2 g_csr[N_EDGES];       // packed (src_bits, weight) sorted by dst
__device__ int g_off[N_NODES + 1];                    // CSR row offsets
__device__ int g_degfill[2 * N_NODES];                // [0..N) degree, [N..2N) fill cursor

// ---------------- CSR build ----------------
__global__ void deg_hist_kernel(const int* __restrict__ dst, int* __restrict__ deg) {
    int e = blockIdx.x * blockDim.x + threadIdx.x;
    if (e < N_EDGES) atomicAdd(&deg[dst[e]], 1);
}

__global__ __launch_bounds__(1024) void scan_kernel(const int* __restrict__ deg,
                                                    int* __restrict__ off) {
    __shared__ int shw[32];
    int t = threadIdx.x;
    int lane = t & 31, wid = t >> 5;
    const int C = (N_NODES + 1023) / 1024;
    int b = t * C;
    int e = min(b + C, N_NODES);
    int s = 0;
    for (int i = b; i < e; i++) s += deg[i];
    int incl = s;
#pragma unroll
    for (int k = 1; k < 32; k <<= 1) {
        int v = __shfl_up_sync(0xffffffffu, incl, k);
        if (lane >= k) incl += v;
    }
    if (lane == 31) shw[wid] = incl;
    __syncthreads();
    if (wid == 0) {
        int ws = shw[lane];
        int wi = ws;
#pragma unroll
        for (int k = 1; k < 32; k <<= 1) {
            int v = __shfl_up_sync(0xffffffffu, wi, k);
            if (lane >= k) wi += v;
        }
        shw[lane] = wi - ws;
    }
    __syncthreads();
    int base = shw[wid] + incl - s;
    for (int i = b; i < e; i++) {
        off[i] = base;
        base += deg[i];
    }
    if (t == 1023) off[N_NODES] = N_EDGES;
}

__global__ void fill_kernel(const int* __restrict__ src,
                            const int* __restrict__ dst,
                            const float* __restrict__ ew,
                            const int* __restrict__ off,
                            int* __restrict__ fill,
                            float2* __restrict__ csr) {
    int e = blockIdx.x * blockDim.x + threadIdx.x;
    if (e >= N_EDGES) return;
    int d = dst[e];
    int pos = off[d] + atomicAdd(&fill[d], 1);
    csr[pos] = make_float2(__int_as_float(src[e]), ew[e]);
}

// ---------------- BatchNorm statistics ----------------
__global__ void bn_stats_kernel(const float* __restrict__ h) {
    float s[5] = {0, 0, 0, 0, 0}, q[5] = {0, 0, 0, 0, 0};
    int stride = gridDim.x * blockDim.x;
    for (int n = blockIdx.x * blockDim.x + threadIdx.x; n < N_NODES; n += stride) {
#pragma unroll
        for (int i = 0; i < 5; i++) {
            float v = h[n * 5 + i];
            s[i] += v;
            q[i] += v * v;
        }
    }
#pragma unroll
    for (int k = 16; k > 0; k >>= 1) {
#pragma unroll
        for (int i = 0; i < 5; i++) {
            s[i] += __shfl_down_sync(0xffffffffu, s[i], k);
            q[i] += __shfl_down_sync(0xffffffffu, q[i], k);
        }
    }
    __shared__ float sh[10];
    if (threadIdx.x < 10) sh[threadIdx.x] = 0.f;
    __syncthreads();
    if ((threadIdx.x & 31) == 0) {
#pragma unroll
        for (int i = 0; i < 5; i++) {
            atomicAdd(&sh[i], s[i]);
            atomicAdd(&sh[5 + i], q[i]);
        }
    }
    __syncthreads();
    if (threadIdx.x < 10) atomicAdd(&g_bnstats[threadIdx.x], sh[threadIdx.x]);
}

// ------- BN apply + conv1 projection (5x5) -> fp16 y8 -------
__global__ void bn_conv1_kernel(const float* __restrict__ h,
                                const float* __restrict__ gamma,
                                const float* __restrict__ beta,
                                const float* __restrict__ pw,
                                const float* __restrict__ pb,
                                float* __restrict__ x0p,
                                __half* __restrict__ y8) {
    int n = blockIdx.x * blockDim.x + threadIdx.x;
    if (n >= N_NODES) return;
    const float inv_n = 1.f / (float)N_NODES;
    float xr[5];
#pragma unroll
    for (int i = 0; i < 5; i++) {
        float mu = g_bnstats[i] * inv_n;
        float var = g_bnstats[5 + i] * inv_n - mu * mu;
        float sc = rsqrtf(var + EPS_BN) * gamma[i];
        xr[i] = (h[n * 5 + i] - mu) * sc + beta[i];
    }
    float4* x0v = reinterpret_cast<float4*>(x0p + (size_t)n * 8);
    x0v[0] = make_float4(xr[0], xr[1], xr[2], xr[3]);
    x0v[1] = make_float4(xr[4], 0.f, 0.f, 0.f);
    float xp[5];
#pragma unroll
    for (int k = 0; k < 5; k++) {
        float v = pb[k];
#pragma unroll
        for (int i = 0; i < 5; i++) v += xr[i] * pw[i * 5 + k];
        xp[k] = fmaxf(v, 0.f);
    }
    __half2 h0 = __floats2half2_rn(xp[0], xp[1]);
    __half2 h1 = __floats2half2_rn(xp[2], xp[3]);
    __half2 h2 = __floats2half2_rn(xp[4], 0.f);
    __half2 h3 = __floats2half2_rn(0.f, 0.f);
    uint4 pack;
    pack.x = *reinterpret_cast<uint32_t*>(&h0);
    pack.y = *reinterpret_cast<uint32_t*>(&h1);
    pack.z = *reinterpret_cast<uint32_t*>(&h2);
    pack.w = *reinterpret_cast<uint32_t*>(&h3);
    *reinterpret_cast<uint4*>(y8 + (size_t)n * 8) = pack;
}

// ---------------- width-8 fp16 pull gather: warp per node, lane per edge ----------------
__global__ void gather8_kernel(const int* __restrict__ off,
                               const float2* __restrict__ csr,
                               const __half* __restrict__ y8,
                               float* __restrict__ agg8) {
    int gw = (blockIdx.x * blockDim.x + threadIdx.x) >> 5;
    if (gw >= N_NODES) return;
    int lane = threadIdx.x & 31;
    int beg = off[gw], end = off[gw + 1];
    float a0 = 0.f, a1 = 0.f, a2 = 0.f, a3 = 0.f, a4 = 0.f;
    for (int j = beg + lane; j < end; j += 32) {
        float2 rec = __ldg(&csr[j]);
        int s = __float_as_int(rec.x);
        float w = rec.y;
        uint4 raw = *reinterpret_cast<const uint4*>(y8 + (size_t)s * 8);
        float2 f0 = __half22float2(*reinterpret_cast<__half2*>(&raw.x));
        float2 f1 = __half22float2(*reinterpret_cast<__half2*>(&raw.y));
        float2 f2 = __half22float2(*reinterpret_cast<__half2*>(&raw.z));
        a0 += f0.x * w;
        a1 += f0.y * w;
        a2 += f1.x * w;
        a3 += f1.y * w;
        a4 += f2.x * w;
    }
#pragma unroll
    for (int k = 16; k > 0; k >>= 1) {
        a0 += __shfl_xor_sync(0xffffffffu, a0, k);
        a1 += __shfl_xor_sync(0xffffffffu, a1, k);
        a2 += __shfl_xor_sync(0xffffffffu, a2, k);
        a3 += __shfl_xor_sync(0xffffffffu, a3, k);
        a4 += __shfl_xor_sync(0xffffffffu, a4, k);
    }
    if (lane == 0) {
        float4* av = reinterpret_cast<float4*>(agg8 + (size_t)gw * 8);
        av[0] = make_float4(a0, a1, a2, a3);
        av[1] = make_float4(a4, (float)(end - beg), 0.f, 0.f);
    }
}

// ---- width-64 fp16 pull gather: warp per node, lane = half2, 4-edge unroll ----
__global__ __launch_bounds__(256) void gather64_kernel(const int* __restrict__ off,
                                                       const float2* __restrict__ csr,
                                                       const __half* __restrict__ y,
                                                       float* __restrict__ agg) {
    int gw = (blockIdx.x * blockDim.x + threadIdx.x) >> 5;
    if (gw >= N_NODES) return;
    int lane = threadIdx.x & 31;
    int beg = off[gw], end = off[gw + 1];
    float accA = 0.f, accB = 0.f;
    const __half2* yb = reinterpret_cast<const __half2*>(y);
    int j = beg;
    for (; j + 4 <= end; j += 4) {
#pragma unroll
        for (int u = 0; u < 4; u++) {
            float2 rec = __ldg(&csr[j + u]);
            int s = __float_as_int(rec.x);
            float w = rec.y;
            float2 f = __half22float2(yb[(size_t)s * 32 + lane]);
            accA += f.x * w;
            accB += f.y * w;
        }
    }
    for (; j < end; j++) {
        float2 rec = __ldg(&csr[j]);
        int s = __float_as_int(rec.x);
        float w = rec.y;
        float2 f = __half22float2(yb[(size_t)s * 32 + lane]);
        accA += f.x * w;
        accB += f.y * w;
    }
    *reinterpret_cast<float2*>(agg + (size_t)gw * 64 + lane * 2) = make_float2(accA, accB);
}

// ------- conv1 finalize: out64 = mean5@lw + lb + x0@rw ; norm ; relu -------
__global__ __launch_bounds__(128) void fin1_kernel(const float* __restrict__ x0p,
                                                   const float* __restrict__ agg8,
                                                   const float* __restrict__ lw,
                                                   const float* __restrict__ lb,
                                                   const float* __restrict__ rw,
                                                   float* __restrict__ x1,
                                                   float* __restrict__ cinv_out) {
    __shared__ float4 s_lw[80], s_rw[80], s_lb[16];
    int t = threadIdx.x;
    if (t < 80) {
        s_lw[t] = reinterpret_cast<const float4*>(lw)[t];
        s_rw[t] = reinterpret_cast<const float4*>(rw)[t];
    }
    if (t < 16) s_lb[t] = reinterpret_cast<const float4*>(lb)[t];
    __syncthreads();
    int n = blockIdx.x * 128 + t;
    if (n >= N_NODES) return;

    const float4* av = reinterpret_cast<const float4*>(agg8 + (size_t)n * 8);
    float4 a0 = av[0], a1 = av[1];
    float ci = 1.f / fmaxf(a1.y, 1.f);
    cinv_out[n] = ci;
    float m[5] = {a0.x * ci, a0.y * ci, a0.z * ci, a0.w * ci, a1.x * ci};
    const float4* xv = reinterpret_cast<const float4*>(x0p + (size_t)n * 8);
    float4 x0a = xv[0], x0b = xv[1];
    float xr[5] = {x0a.x, x0a.y, x0a.z, x0a.w, x0b.x};

    float ss = 0.f;
#pragma unroll
    for (int oq = 0; oq < 16; oq++) {
        float4 v = s_lb[oq];
#pragma unroll
        for (int i = 0; i < 5; i++) {
            float4 w1 = s_lw[i * 16 + oq];
            float4 w2 = s_rw[i * 16 + oq];
            v.x += m[i] * w1.x + xr[i] * w2.x;
            v.y += m[i] * w1.y + xr[i] * w2.y;
            v.z += m[i] * w1.z + xr[i] * w2.z;
            v.w += m[i] * w1.w + xr[i] * w2.w;
        }
        ss += v.x * v.x + v.y * v.y + v.z * v.z + v.w * v.w;
    }
    float sc = 1.f / fmaxf(sqrtf(ss), EPS_NORM);
    float4* xo = reinterpret_cast<float4*>(x1 + (size_t)n * 64);
#pragma unroll
    for (int oq = 0; oq < 16; oq++) {
        float4 v = s_lb[oq];
#pragma unroll
        for (int i = 0; i < 5; i++) {
            float4 w1 = s_lw[i * 16 + oq];
            float4 w2 = s_rw[i * 16 + oq];
            v.x += m[i] * w1.x + xr[i] * w2.x;
            v.y += m[i] * w1.y + xr[i] * w2.y;
            v.z += m[i] * w1.z + xr[i] * w2.z;
            v.w += m[i] * w1.w + xr[i] * w2.w;
        }
        xo[oq] = make_float4(fmaxf(v.x * sc, 0.f), fmaxf(v.y * sc, 0.f),
                             fmaxf(v.z * sc, 0.f), fmaxf(v.w * sc, 0.f));
    }
}

// -------- y(half) = relu(x@pw + pb) @ lw  (64 -> 64 -> OUT2) --------
template <int OUT2>
__global__ __launch_bounds__(128) void proj_lw_kernel(const float* __restrict__ x,
                                                      const float* __restrict__ pw,
                                                      const float* __restrict__ pb,
                                                      const float* __restrict__ lw,
                                                      __half* __restrict__ y) {
    constexpr int OUTP = (OUT2 == 64) ? 64 : 8;
    constexpr int YS = (OUT2 == 64) ? 64 : 8;
    constexpr int NPB = 32;
    constexpr int XS = 36;
    __shared__ float s_w[64 * 64];
    __shared__ float s_x[64 * XS];
    __shared__ float s_xp[64 * XS];
    __shared__ float s_pb[64];
    const int t = threadIdx.x;
    const int n0 = blockIdx.x * NPB;

    for (int i4 = t; i4 < 1024; i4 += 128)
        reinterpret_cast<float4*>(s_w)[i4] = reinterpret_cast<const float4*>(pw)[i4];
    if (t < 64) s_pb[t] = pb[t];
    for (int idx = t; idx < NPB * 64; idx += 128) {
        int n = idx >> 6, i = idx & 63;
        s_x[i * XS + n] = x[(size_t)(n0 + n) * 64 + i];
    }
    __syncthreads();

    const int oq = t & 15, nq = t >> 4;
    float acc[4][4];
#pragma unroll
    for (int a = 0; a < 4; a++)
#pragma unroll
        for (int b = 0; b < 4; b++) acc[a][b] = 0.f;

#pragma unroll 8
    for (int i = 0; i < 64; i++) {
        float4 xv = *reinterpret_cast<const float4*>(&s_x[i * XS + (nq << 2)]);
        float4 wv = *reinterpret_cast<const float4*>(&s_w[(i << 6) + (oq << 2)]);
        acc[0][0] += xv.x * wv.x; acc[0][1] += xv.x * wv.y; acc[0][2] += xv.x * wv.z; acc[0][3] += xv.x * wv.w;
        acc[1][0] += xv.y * wv.x; acc[1][1] += xv.y * wv.y; acc[1][2] += xv.y * wv.z; acc[1][3] += xv.y * wv.w;
        acc[2][0] += xv.z * wv.x; acc[2][1] += xv.z * wv.y; acc[2][2] += xv.z * wv.z; acc[2][3] += xv.z * wv.w;
        acc[3][0] += xv.w * wv.x; acc[3][1] += xv.w * wv.y; acc[3][2] += xv.w * wv.z; acc[3][3] += xv.w * wv.w;
    }
#pragma unroll
    for (int dk = 0; dk < 4; dk++) {
        float b = s_pb[(oq << 2) + dk];
#pragma unroll
        for (int dn = 0; dn < 4; dn++) {
            s_xp[((oq << 2) + dk) * XS + (nq << 2) + dn] = fmaxf(acc[dn][dk] + b, 0.f);
        }
    }
    __syncthreads();

    if (OUT2 == 64) {
        for (int i4 = t; i4 < 1024; i4 += 128)
            reinterpret_cast<float4*>(s_w)[i4] = reinterpret_cast<const float4*>(lw)[i4];
    } else {
        for (int idx = t; idx < 64 * 8; idx += 128) s_w[idx] = 0.f;
        __syncthreads();
        for (int idx = t; idx < 64 * 5; idx += 128) s_w[(idx / 5) * 8 + (idx % 5)] = lw[idx];
    }
    __syncthreads();

    constexpr int OQ2 = OUTP / 4;
    if (oq < OQ2) {
        float a2[4][4];
#pragma unroll
        for (int a = 0; a < 4; a++)
#pragma unroll
            for (int b = 0; b < 4; b++) a2[a][b] = 0.f;
#pragma unroll 8
        for (int i = 0; i < 64; i++) {
            float4 xv = *reinterpret_cast<const float4*>(&s_xp[i * XS + (nq << 2)]);
            float4 wv = *reinterpret_cast<const float4*>(&s_w[i * OUTP + (oq << 2)]);
            a2[0][0] += xv.x * wv.x; a2[0][1] += xv.x * wv.y; a2[0][2] += xv.x * wv.z; a2[0][3] += xv.x * wv.w;
            a2[1][0] += xv.y * wv.x; a2[1][1] += xv.y * wv.y; a2[1][2] += xv.y * wv.z; a2[1][3] += xv.y * wv.w;
            a2[2][0] += xv.z * wv.x; a2[2][1] += xv.z * wv.y; a2[2][2] += xv.z * wv.z; a2[2][3] += xv.z * wv.w;
            a2[3][0] += xv.w * wv.x; a2[3][1] += xv.w * wv.y; a2[3][2] += xv.w * wv.z; a2[3][3] += xv.w * wv.w;
        }
#pragma unroll
        for (int dn = 0; dn < 4; dn++) {
            __half2 h0 = __floats2half2_rn(a2[dn][0], a2[dn][1]);
            __half2 h1 = __floats2half2_rn(a2[dn][2], a2[dn][3]);
            uint2 pack;
            pack.x = *reinterpret_cast<uint32_t*>(&h0);
            pack.y = *reinterpret_cast<uint32_t*>(&h1);
            *reinterpret_cast<uint2*>(y + (size_t)(n0 + (nq << 2) + dn) * YS + (oq << 2)) = pack;
        }
    }
}

// ------- conv2 finalize: out = agg*cinv + lb + x@rw ; norm ; relu -------
__global__ __launch_bounds__(128) void fin64_kernel(const float* __restrict__ x,
                                                    const float* __restrict__ agg,
                                                    const float* __restrict__ cinv,
                                                    const float* __restrict__ rw,
                                                    const float* __restrict__ lb,
                                                    float* __restrict__ out) {
    constexpr int NPB = 32;
    constexpr int XS = 36;
    __shared__ float s_w[64 * 64];
    __shared__ float s_x[64 * XS];
    __shared__ float s_lb[64];
    const int t = threadIdx.x;
    const int n0 = blockIdx.x * NPB;

    for (int i4 = t; i4 < 1024; i4 += 128)
        reinterpret_cast<float4*>(s_w)[i4] = reinterpret_cast<const float4*>(rw)[i4];
    if (t < 64) s_lb[t] = lb[t];
    for (int idx = t; idx < NPB * 64; idx += 128) {
        int n = idx >> 6, i = idx & 63;
        s_x[i * XS + n] = x[(size_t)(n0 + n) * 64 + i];
    }
    __syncthreads();

    const int oq = t & 15, nq = t >> 4;
    float acc[4][4];
#pragma unroll
    for (int a = 0; a < 4; a++)
#pragma unroll
        for (int b = 0; b < 4; b++) acc[a][b] = 0.f;
#pragma unroll 8
    for (int i = 0; i < 64; i++) {
        float4 xv = *reinterpret_cast<const float4*>(&s_x[i * XS + (nq << 2)]);
        float4 wv = *reinterpret_cast<const float4*>(&s_w[(i << 6) + (oq << 2)]);
        acc[0][0] += xv.x * wv.x; acc[0][1] += xv.x * wv.y; acc[0][2] += xv.x * wv.z; acc[0][3] += xv.x * wv.w;
        acc[1][0] += xv.y * wv.x; acc[1][1] += xv.y * wv.y; acc[1][2] += xv.y * wv.z; acc[1][3] += xv.y * wv.w;
        acc[2][0] += xv.z * wv.x; acc[2][1] += xv.z * wv.y; acc[2][2] += xv.z * wv.z; acc[2][3] += xv.z * wv.w;
        acc[3][0] += xv.w * wv.x; acc[3][1] += xv.w * wv.y; acc[3][2] += xv.w * wv.z; acc[3][3] += xv.w * wv.w;
    }

    float lb0 = s_lb[(oq << 2) + 0], lb1 = s_lb[(oq << 2) + 1];
    float lb2 = s_lb[(oq << 2) + 2], lb3 = s_lb[(oq << 2) + 3];
#pragma unroll
    for (int dn = 0; dn < 4; dn++) {
        int n = n0 + (nq << 2) + dn;
        float ci = cinv[n];
        float4 ag = *reinterpret_cast<const float4*>(&agg[(size_t)n * 64 + (oq << 2)]);
        float v0 = acc[dn][0] + lb0 + ag.x * ci;
        float v1 = acc[dn][1] + lb1 + ag.y * ci;
        float v2 = acc[dn][2] + lb2 + ag.z * ci;
        float v3 = acc[dn][3] + lb3 + ag.w * ci;
        float ss = v0 * v0 + v1 * v1 + v2 * v2 + v3 * v3;
        ss += __shfl_down_sync(0xffffffffu, ss, 8, 16);
        ss += __shfl_down_sync(0xffffffffu, ss, 4, 16);
        ss += __shfl_down_sync(0xffffffffu, ss, 2, 16);
        ss += __shfl_down_sync(0xffffffffu, ss, 1, 16);
        ss = __shfl_sync(0xffffffffu, ss, 0, 16);
        float sc = 1.f / fmaxf(sqrtf(ss), EPS_NORM);
        float4 o4 = make_float4(fmaxf(v0 * sc, 0.f), fmaxf(v1 * sc, 0.f),
                                fmaxf(v2 * sc, 0.f), fmaxf(v3 * sc, 0.f));
        *reinterpret_cast<float4*>(&out[(size_t)n * 64 + (oq << 2)]) = o4;
    }
}

// ------- conv3 finalize: out5 = agg*cinv + lb + x2@rw ; norm (no relu) -------
__global__ __launch_bounds__(128) void fin3_kernel(const float* __restrict__ x2,
                                                   const float* __restrict__ agg8,
                                                   const float* __restrict__ cinv,
                                                   const float* __restrict__ rw,
                                                   const float* __restrict__ lb,
                                                   float* __restrict__ out) {
    __shared__ float s_rw[64 * 8];
    __shared__ float s_lb[8];
    int t = threadIdx.x;
    for (int idx = t; idx < 320; idx += 128) s_rw[(idx / 5) * 8 + (idx % 5)] = rw[idx];
    if (t < 5) s_lb[t] = lb[t];
    __syncthreads();
    int n = blockIdx.x * 128 + t;
    if (n >= N_NODES) return;

    float ci = cinv[n];
    const float4* av = reinterpret_cast<const float4*>(agg8 + (size_t)n * 8);
    float4 a0 = av[0], a1 = av[1];
    float4 vf = make_float4(s_lb[0] + a0.x * ci, s_lb[1] + a0.y * ci,
                            s_lb[2] + a0.z * ci, s_lb[3] + a0.w * ci);
    float v4 = s_lb[4] + a1.x * ci;

    const float4* xr = reinterpret_cast<const float4*>(x2 + (size_t)n * 64);
#pragma unroll
    for (int iq = 0; iq < 16; iq++) {
        float4 xv = xr[iq];
        float xs[4] = {xv.x, xv.y, xv.z, xv.w};
#pragma unroll
        for (int c = 0; c < 4; c++) {
            int i = iq * 4 + c;
            float4 w = *reinterpret_cast<const float4*>(&s_rw[i * 8]);
            float w4 = s_rw[i * 8 + 4];
            vf.x += xs[c] * w.x;
            vf.y += xs[c] * w.y;
            vf.z += xs[c] * w.z;
            vf.w += xs[c] * w.w;
            v4 += xs[c] * w4;
        }
    }
    float ss = vf.x * vf.x + vf.y * vf.y + vf.z * vf.z + vf.w * vf.w + v4 * v4;
    float sc = 1.f / fmaxf(sqrtf(ss), EPS_NORM);
    float* o = out + (size_t)n * 5;
    o[0] = vf.x * sc;
    o[1] = vf.y * sc;
    o[2] = vf.z * sc;
    o[3] = vf.w * sc;
    o[4] = v4 * sc;
}

// ---------------- host launcher ----------------
extern "C" void kernel_launch(void* const* d_in, const int* in_sizes, int n_in,
                              void* d_out, int out_size) {
    const float* h = (const float*)d_in[0];
    const int* ei = (const int*)d_in[1];
    const float* ew = (const float*)d_in[2];
    const float* gamma = (const float*)d_in[3];
    const float* beta = (const float*)d_in[4];
    const float* c1_pw = (const float*)d_in[5];
    const float* c1_pb = (const float*)d_in[6];
    const float* c1_lw = (const float*)d_in[7];
    const float* c1_lb = (const float*)d_in[8];
    const float* c1_rw = (const float*)d_in[9];
    const float* c2_pw = (const float*)d_in[10];
    const float* c2_pb = (const float*)d_in[11];
    const float* c2_lw = (const float*)d_in[12];
    const float* c2_lb = (const float*)d_in[13];
    const float* c2_rw = (const float*)d_in[14];
    const float* c3_pw = (const float*)d_in[15];
    const float* c3_pb = (const float*)d_in[16];
    const float* c3_lw = (const float*)d_in[17];
    const float* c3_lb = (const float*)d_in[18];
    const float* c3_rw = (const float*)d_in[19];
    float* out = (float*)d_out;

    const int* src = ei;
    const int* dst = ei + N_EDGES;

    float *x0, *x1, *x2, *agg, *agg8, *cinv, *stats;
    __half* yh;
    float2* csr;
    int *off, *degfill;
    cudaGetSymbolAddress((void**)&x0, g_x0);
    cudaGetSymbolAddress((void**)&x1, g_x1);
    cudaGetSymbolAddress((void**)&x2, g_x2);
    cudaGetSymbolAddress((void**)&yh, g_yh);
    cudaGetSymbolAddress((void**)&agg, g_agg);
    cudaGetSymbolAddress((void**)&agg8, g_agg8);
    cudaGetSymbolAddress((void**)&cinv, g_cinv);
    cudaGetSymbolAddress((void**)&stats, g_bnstats);
    cudaGetSymbolAddress((void**)&csr, g_csr);
    cudaGetSymbolAddress((void**)&off, g_off);
    cudaGetSymbolAddress((void**)&degfill, g_degfill);

    int* deg = degfill;
    int* fill = degfill + N_NODES;

    cudaMemsetAsync(stats, 0, sizeof(float) * 16, 0);
    cudaMemsetAsync(degfill, 0, sizeof(int) * 2 * N_NODES, 0);

    // CSR build (amortized across all three convs)
    deg_hist_kernel<<<(N_EDGES + 255) / 256, 256>>>(dst, deg);
    scan_kernel<<<1, 1024>>>(deg, off);
    fill_kernel<<<(N_EDGES + 255) / 256, 256>>>(src, dst, ew, off, fill, csr);

    // BatchNorm + conv1 projection (fp16 y8)
    bn_stats_kernel<<<296, 256>>>(h);
    bn_conv1_kernel<<<(N_NODES + 255) / 256, 256>>>(h, gamma, beta, c1_pw, c1_pb, x0, yh);

    // conv1: fp16 pull-gather (width 5) + finalize
    gather8_kernel<<<(N_NODES * 32 + 255) / 256, 256>>>(off, csr, yh, agg8);
    fin1_kernel<<<(N_NODES + 127) / 128, 128>>>(x0, agg8, c1_lw, c1_lb, c1_rw, x1, cinv);

    // conv2
    proj_lw_kernel<64><<<N_NODES / 32, 128>>>(x1, c2_pw, c2_pb, c2_lw, yh);
    gather64_kernel<<<(N_NODES * 32 + 255) / 256, 256>>>(off, csr, yh, agg);
    fin64_kernel<<<N_NODES / 32, 128>>>(x1, agg, cinv, c2_rw, c2_lb, x2);

    // conv3
    proj_lw_kernel<5><<<N_NODES / 32, 128>>>(x2, c3_pw, c3_pb, c3_lw, yh);
    gather8_kernel<<<(N_NODES * 32 + 255) / 256, 256>>>(off, csr, yh, agg8);
    fin3_kernel<<<(N_NODES + 127) / 128, 128>>>(x2, agg8, cinv, c3_rw, c3_lb, out);
}

// round 5
// speedup vs baseline: 1.1648x; 1.1399x over previous
#include <cuda_runtime.h>
#include <cuda_fp16.h>
#include <cstdint>
#include <math.h>

#define N_NODES 100000
#define N_EDGES 3200000
#define EPS_BN 1e-5f
#define EPS_NORM 1e-12f

// ---------------- device scratch (no allocation allowed) ----------------
__device__ __align__(16) float g_x0[N_NODES * 8];     // BN output (padded stride 8)
__device__ __align__(16) float g_x1[N_NODES * 64];    // conv1 output
__device__ __align__(16) float g_x2[N_NODES * 64];    // conv2 output
__device__ __align__(16) __half g_yh[N_NODES * 64];   // fp16 projected features (stride 64 or 8)
__device__ __align__(16) float g_agg[N_NODES * 64];   // conv2 accumulator
__device__ __align__(32) float g_agg8[N_NODES * 8];   // conv1/conv3 accumulator (5 feats + cnt)
__device__ float g_cinv[N_NODES];                     // 1/max(cnt,1)
__device__ __align__(16) float g_part[148 * 16];      // BN per-block partials (no memset needed)

// ---------------- vector reductions ----------------
__device__ __forceinline__ void red_add_v4(float* p, float4 v) {
    asm volatile("red.global.add.v4.f32 [%0], {%1,%2,%3,%4};"
                 :: "l"(p), "f"(v.x), "f"(v.y), "f"(v.z), "f"(v.w) : "memory");
}
__device__ __forceinline__ void red_add_v2(float* p, float a, float b) {
    asm volatile("red.global.add.v2.f32 [%0], {%1,%2};"
                 :: "l"(p), "f"(a), "f"(b) : "memory");
}
__device__ __forceinline__ void red_add_f32(float* p, float a) {
    asm volatile("red.global.add.f32 [%0], %1;"
                 :: "l"(p), "f"(a) : "memory");
}

// ------- BatchNorm statistics: per-block partials (no pre-zeroing) -------
__global__ __launch_bounds__(256) void bn_stats_kernel(const float* __restrict__ h,
                                                       float* __restrict__ part) {
    float s[5] = {0, 0, 0, 0, 0}, q[5] = {0, 0, 0, 0, 0};
    int stride = gridDim.x * blockDim.x;
    for (int n = blockIdx.x * blockDim.x + threadIdx.x; n < N_NODES; n += stride) {
#pragma unroll
        for (int i = 0; i < 5; i++) {
            float v = h[n * 5 + i];
            s[i] += v;
            q[i] += v * v;
        }
    }
#pragma unroll
    for (int k = 16; k > 0; k >>= 1) {
#pragma unroll
        for (int i = 0; i < 5; i++) {
            s[i] += __shfl_down_sync(0xffffffffu, s[i], k);
            q[i] += __shfl_down_sync(0xffffffffu, q[i], k);
        }
    }
    __shared__ float sh[10];
    if (threadIdx.x < 10) sh[threadIdx.x] = 0.f;
    __syncthreads();
    if ((threadIdx.x & 31) == 0) {
#pragma unroll
        for (int i = 0; i < 5; i++) {
            atomicAdd(&sh[i], s[i]);
            atomicAdd(&sh[5 + i], q[i]);
        }
    }
    __syncthreads();
    if (threadIdx.x < 10) part[blockIdx.x * 16 + threadIdx.x] = sh[threadIdx.x];
}

// ------- BN apply + conv1 projection (5x5) -> fp16 y8 ; zero agg8 -------
__global__ __launch_bounds__(256) void bn_conv1_kernel(const float* __restrict__ h,
                                                       const float* __restrict__ part,
                                                       const float* __restrict__ gamma,
                                                       const float* __restrict__ beta,
                                                       const float* __restrict__ pw,
                                                       const float* __restrict__ pb,
                                                       float* __restrict__ x0p,
                                                       __half* __restrict__ y8,
                                                       float* __restrict__ agg8) {
    // reduce the 148 per-block partials (10 values each) inside every block
    __shared__ float s_warp[8][10];
    __shared__ float s_stats[10];
    int t = threadIdx.x;
    int lane = t & 31, wid = t >> 5;
    {
        float v[10];
#pragma unroll
        for (int i = 0; i < 10; i++) v[i] = 0.f;
        if (t < 148) {
#pragma unroll
            for (int i = 0; i < 10; i++) v[i] = part[t * 16 + i];
        }
#pragma unroll
        for (int k = 16; k > 0; k >>= 1) {
#pragma unroll
            for (int i = 0; i < 10; i++) v[i] += __shfl_down_sync(0xffffffffu, v[i], k);
        }
        if (lane == 0) {
#pragma unroll
            for (int i = 0; i < 10; i++) s_warp[wid][i] = v[i];
        }
    }
    __syncthreads();
    if (t < 10) {
        float acc = 0.f;
#pragma unroll
        for (int w = 0; w < 8; w++) acc += s_warp[w][t];
        s_stats[t] = acc;
    }
    __syncthreads();

    int n = blockIdx.x * blockDim.x + t;
    if (n >= N_NODES) return;
    const float inv_n = 1.f / (float)N_NODES;
    float xr[5];
#pragma unroll
    for (int i = 0; i < 5; i++) {
        float mu = s_stats[i] * inv_n;
        float var = s_stats[5 + i] * inv_n - mu * mu;
        float sc = rsqrtf(var + EPS_BN) * gamma[i];
        xr[i] = (h[n * 5 + i] - mu) * sc + beta[i];
    }
    float4* x0v = reinterpret_cast<float4*>(x0p + (size_t)n * 8);
    x0v[0] = make_float4(xr[0], xr[1], xr[2], xr[3]);
    x0v[1] = make_float4(xr[4], 0.f, 0.f, 0.f);
    float xp[5];
#pragma unroll
    for (int k = 0; k < 5; k++) {
        float v = pb[k];
#pragma unroll
        for (int i = 0; i < 5; i++) v += xr[i] * pw[i * 5 + k];
        xp[k] = fmaxf(v, 0.f);
    }
    __half2 h0 = __floats2half2_rn(xp[0], xp[1]);
    __half2 h1 = __floats2half2_rn(xp[2], xp[3]);
    __half2 h2 = __floats2half2_rn(xp[4], 0.f);
    uint4 pack;
    pack.x = *reinterpret_cast<uint32_t*>(&h0);
    pack.y = *reinterpret_cast<uint32_t*>(&h1);
    pack.z = *reinterpret_cast<uint32_t*>(&h2);
    pack.w = 0u;
    *reinterpret_cast<uint4*>(y8 + (size_t)n * 8) = pack;
    // zero agg8 row for the upcoming scatter
    float4* av = reinterpret_cast<float4*>(agg8 + (size_t)n * 8);
    float4 z = make_float4(0.f, 0.f, 0.f, 0.f);
    av[0] = z;
    av[1] = z;
}

// -------- width-8 push scatter (fp16 reads, fp32 atomics) --------
template <bool ADD_CNT>
__global__ void scatter8_kernel(const int* __restrict__ src,
                                const int* __restrict__ dst,
                                const float* __restrict__ ew,
                                const __half* __restrict__ y8,
                                float* __restrict__ agg8) {
    int stride = gridDim.x * blockDim.x;
    for (int e = blockIdx.x * blockDim.x + threadIdx.x; e < N_EDGES; e += stride) {
        int s = __ldg(&src[e]);
        int d = __ldg(&dst[e]);
        float w = __ldg(&ew[e]);
        uint4 raw = *reinterpret_cast<const uint4*>(y8 + (size_t)s * 8);
        float2 f0 = __half22float2(*reinterpret_cast<__half2*>(&raw.x));
        float2 f1 = __half22float2(*reinterpret_cast<__half2*>(&raw.y));
        float2 f2 = __half22float2(*reinterpret_cast<__half2*>(&raw.z));
        red_add_v4(agg8 + (size_t)d * 8,
                   make_float4(f0.x * w, f0.y * w, f1.x * w, f1.y * w));
        if (ADD_CNT)
            red_add_v2(agg8 + (size_t)d * 8 + 4, f2.x * w, 1.0f);
        else
            red_add_f32(agg8 + (size_t)d * 8 + 4, f2.x * w);
    }
}

// -------- width-64 push scatter (fp16 reads): warp handles 2 edges --------
__global__ void scatter64_kernel(const int* __restrict__ src,
                                 const int* __restrict__ dst,
                                 const float* __restrict__ ew,
                                 const __half* __restrict__ y,
                                 float* __restrict__ agg) {
    int lane = threadIdx.x & 31;
    int warp = (blockIdx.x * blockDim.x + threadIdx.x) >> 5;
    int nwarps = (gridDim.x * blockDim.x) >> 5;
    int half = lane >> 4;         // which edge of the pair
    int fq = (lane & 15) << 2;    // feature offset (4 halves)
    const int npairs = N_EDGES / 2;
    for (int p = warp; p < npairs; p += nwarps) {
        int e = 2 * p + half;
        int s = __ldg(&src[e]);
        int d = __ldg(&dst[e]);
        float w = __ldg(&ew[e]);
        uint2 raw = *reinterpret_cast<const uint2*>(y + (size_t)s * 64 + fq);
        float2 f0 = __half22float2(*reinterpret_cast<__half2*>(&raw.x));
        float2 f1 = __half22float2(*reinterpret_cast<__half2*>(&raw.y));
        red_add_v4(agg + (size_t)d * 64 + fq,
                   make_float4(f0.x * w, f0.y * w, f1.x * w, f1.y * w));
    }
}

// ------- conv1 finalize: out64 = mean5@lw + lb + x0@rw ; norm ; relu -------
__global__ __launch_bounds__(128) void fin1_kernel(const float* __restrict__ x0p,
                                                   const float* __restrict__ agg8,
                                                   const float* __restrict__ lw,
                                                   const float* __restrict__ lb,
                                                   const float* __restrict__ rw,
                                                   float* __restrict__ x1,
                                                   float* __restrict__ cinv_out) {
    __shared__ float4 s_lw[80], s_rw[80], s_lb[16];
    int t = threadIdx.x;
    if (t < 80) {
        s_lw[t] = reinterpret_cast<const float4*>(lw)[t];
        s_rw[t] = reinterpret_cast<const float4*>(rw)[t];
    }
    if (t < 16) s_lb[t] = reinterpret_cast<const float4*>(lb)[t];
    __syncthreads();
    int n = blockIdx.x * 128 + t;
    if (n >= N_NODES) return;

    const float4* av = reinterpret_cast<const float4*>(agg8 + (size_t)n * 8);
    float4 a0 = av[0], a1 = av[1];
    float ci = 1.f / fmaxf(a1.y, 1.f);
    cinv_out[n] = ci;
    float m[5] = {a0.x * ci, a0.y * ci, a0.z * ci, a0.w * ci, a1.x * ci};
    const float4* xv = reinterpret_cast<const float4*>(x0p + (size_t)n * 8);
    float4 x0a = xv[0], x0b = xv[1];
    float xr[5] = {x0a.x, x0a.y, x0a.z, x0a.w, x0b.x};

    float ss = 0.f;
#pragma unroll
    for (int oq = 0; oq < 16; oq++) {
        float4 v = s_lb[oq];
#pragma unroll
        for (int i = 0; i < 5; i++) {
            float4 w1 = s_lw[i * 16 + oq];
            float4 w2 = s_rw[i * 16 + oq];
            v.x += m[i] * w1.x + xr[i] * w2.x;
            v.y += m[i] * w1.y + xr[i] * w2.y;
            v.z += m[i] * w1.z + xr[i] * w2.z;
            v.w += m[i] * w1.w + xr[i] * w2.w;
        }
        ss += v.x * v.x + v.y * v.y + v.z * v.z + v.w * v.w;
    }
    float sc = 1.f / fmaxf(sqrtf(ss), EPS_NORM);
    float4* xo = reinterpret_cast<float4*>(x1 + (size_t)n * 64);
#pragma unroll
    for (int oq = 0; oq < 16; oq++) {
        float4 v = s_lb[oq];
#pragma unroll
        for (int i = 0; i < 5; i++) {
            float4 w1 = s_lw[i * 16 + oq];
            float4 w2 = s_rw[i * 16 + oq];
            v.x += m[i] * w1.x + xr[i] * w2.x;
            v.y += m[i] * w1.y + xr[i] * w2.y;
            v.z += m[i] * w1.z + xr[i] * w2.z;
            v.w += m[i] * w1.w + xr[i] * w2.w;
        }
        xo[oq] = make_float4(fmaxf(v.x * sc, 0.f), fmaxf(v.y * sc, 0.f),
                             fmaxf(v.z * sc, 0.f), fmaxf(v.w * sc, 0.f));
    }
}

// -------- y(half) = relu(x@pw + pb) @ lw  (64 -> 64 -> OUT2) --------
// optionally zeroes a per-block slice of an accumulator (for next scatter)
template <int OUT2>
__global__ __launch_bounds__(128) void proj_lw_kernel(const float* __restrict__ x,
                                                      const float* __restrict__ pw,
                                                      const float* __restrict__ pb,
                                                      const float* __restrict__ lw,
                                                      __half* __restrict__ y,
                                                      float* __restrict__ zero_base,
                                                      int zero_f4_per_blk) {
    constexpr int OUTP = (OUT2 == 64) ? 64 : 8;
    constexpr int YS = (OUT2 == 64) ? 64 : 8;
    constexpr int NPB = 32;
    constexpr int XS = 36;
    __shared__ float s_w[64 * 64];
    __shared__ float s_x[64 * XS];
    __shared__ float s_xp[64 * XS];
    __shared__ float s_pb[64];
    const int t = threadIdx.x;
    const int n0 = blockIdx.x * NPB;

    if (zero_base) {
        float4 z = make_float4(0.f, 0.f, 0.f, 0.f);
        float4* zb = reinterpret_cast<float4*>(zero_base) + (size_t)blockIdx.x * zero_f4_per_blk;
        for (int i = t; i < zero_f4_per_blk; i += 128) zb[i] = z;
    }

    for (int i4 = t; i4 < 1024; i4 += 128)
        reinterpret_cast<float4*>(s_w)[i4] = reinterpret_cast<const float4*>(pw)[i4];
    if (t < 64) s_pb[t] = pb[t];
    for (int idx = t; idx < NPB * 64; idx += 128) {
        int n = idx >> 6, i = idx & 63;
        s_x[i * XS + n] = x[(size_t)(n0 + n) * 64 + i];
    }
    __syncthreads();

    const int oq = t & 15, nq = t >> 4;
    float acc[4][4];
#pragma unroll
    for (int a = 0; a < 4; a++)
#pragma unroll
        for (int b = 0; b < 4; b++) acc[a][b] = 0.f;

#pragma unroll 8
    for (int i = 0; i < 64; i++) {
        float4 xv = *reinterpret_cast<const float4*>(&s_x[i * XS + (nq << 2)]);
        float4 wv = *reinterpret_cast<const float4*>(&s_w[(i << 6) + (oq << 2)]);
        acc[0][0] += xv.x * wv.x; acc[0][1] += xv.x * wv.y; acc[0][2] += xv.x * wv.z; acc[0][3] += xv.x * wv.w;
        acc[1][0] += xv.y * wv.x; acc[1][1] += xv.y * wv.y; acc[1][2] += xv.y * wv.z; acc[1][3] += xv.y * wv.w;
        acc[2][0] += xv.z * wv.x; acc[2][1] += xv.z * wv.y; acc[2][2] += xv.z * wv.z; acc[2][3] += xv.z * wv.w;
        acc[3][0] += xv.w * wv.x; acc[3][1] += xv.w * wv.y; acc[3][2] += xv.w * wv.z; acc[3][3] += xv.w * wv.w;
    }
#pragma unroll
    for (int dk = 0; dk < 4; dk++) {
        float b = s_pb[(oq << 2) + dk];
#pragma unroll
        for (int dn = 0; dn < 4; dn++) {
            s_xp[((oq << 2) + dk) * XS + (nq << 2) + dn] = fmaxf(acc[dn][dk] + b, 0.f);
        }
    }
    __syncthreads();

    if (OUT2 == 64) {
        for (int i4 = t; i4 < 1024; i4 += 128)
            reinterpret_cast<float4*>(s_w)[i4] = reinterpret_cast<const float4*>(lw)[i4];
    } else {
        for (int idx = t; idx < 64 * 8; idx += 128) s_w[idx] = 0.f;
        __syncthreads();
        for (int idx = t; idx < 64 * 5; idx += 128) s_w[(idx / 5) * 8 + (idx % 5)] = lw[idx];
    }
    __syncthreads();

    constexpr int OQ2 = OUTP / 4;
    if (oq < OQ2) {
        float a2[4][4];
#pragma unroll
        for (int a = 0; a < 4; a++)
#pragma unroll
            for (int b = 0; b < 4; b++) a2[a][b] = 0.f;
#pragma unroll 8
        for (int i = 0; i < 64; i++) {
            float4 xv = *reinterpret_cast<const float4*>(&s_xp[i * XS + (nq << 2)]);
            float4 wv = *reinterpret_cast<const float4*>(&s_w[i * OUTP + (oq << 2)]);
            a2[0][0] += xv.x * wv.x; a2[0][1] += xv.x * wv.y; a2[0][2] += xv.x * wv.z; a2[0][3] += xv.x * wv.w;
            a2[1][0] += xv.y * wv.x; a2[1][1] += xv.y * wv.y; a2[1][2] += xv.y * wv.z; a2[1][3] += xv.y * wv.w;
            a2[2][0] += xv.z * wv.x; a2[2][1] += xv.z * wv.y; a2[2][2] += xv.z * wv.z; a2[2][3] += xv.z * wv.w;
            a2[3][0] += xv.w * wv.x; a2[3][1] += xv.w * wv.y; a2[3][2] += xv.w * wv.z; a2[3][3] += xv.w * wv.w;
        }
#pragma unroll
        for (int dn = 0; dn < 4; dn++) {
            __half2 h0 = __floats2half2_rn(a2[dn][0], a2[dn][1]);
            __half2 h1 = __floats2half2_rn(a2[dn][2], a2[dn][3]);
            uint2 pack;
            pack.x = *reinterpret_cast<uint32_t*>(&h0);
            pack.y = *reinterpret_cast<uint32_t*>(&h1);
            *reinterpret_cast<uint2*>(y + (size_t)(n0 + (nq << 2) + dn) * YS + (oq << 2)) = pack;
        }
    }
}

// ------- conv2 finalize: out = agg*cinv + lb + x@rw ; norm ; relu ; zero agg8 -------
__global__ __launch_bounds__(128) void fin64_kernel(const float* __restrict__ x,
                                                    const float* __restrict__ agg,
                                                    const float* __restrict__ cinv,
                                                    const float* __restrict__ rw,
                                                    const float* __restrict__ lb,
                                                    float* __restrict__ out,
                                                    float* __restrict__ agg8z) {
    constexpr int NPB = 32;
    constexpr int XS = 36;
    __shared__ float s_w[64 * 64];
    __shared__ float s_x[64 * XS];
    __shared__ float s_lb[64];
    const int t = threadIdx.x;
    const int n0 = blockIdx.x * NPB;

    if (t < 64) {
        float4 z = make_float4(0.f, 0.f, 0.f, 0.f);
        reinterpret_cast<float4*>(agg8z + (size_t)n0 * 8)[t] = z;
    }

    for (int i4 = t; i4 < 1024; i4 += 128)
        reinterpret_cast<float4*>(s_w)[i4] = reinterpret_cast<const float4*>(rw)[i4];
    if (t < 64) s_lb[t] = lb[t];
    for (int idx = t; idx < NPB * 64; idx += 128) {
        int n = idx >> 6, i = idx & 63;
        s_x[i * XS + n] = x[(size_t)(n0 + n) * 64 + i];
    }
    __syncthreads();

    const int oq = t & 15, nq = t >> 4;
    float acc[4][4];
#pragma unroll
    for (int a = 0; a < 4; a++)
#pragma unroll
        for (int b = 0; b < 4; b++) acc[a][b] = 0.f;
#pragma unroll 8
    for (int i = 0; i < 64; i++) {
        float4 xv = *reinterpret_cast<const float4*>(&s_x[i * XS + (nq << 2)]);
        float4 wv = *reinterpret_cast<const float4*>(&s_w[(i << 6) + (oq << 2)]);
        acc[0][0] += xv.x * wv.x; acc[0][1] += xv.x * wv.y; acc[0][2] += xv.x * wv.z; acc[0][3] += xv.x * wv.w;
        acc[1][0] += xv.y * wv.x; acc[1][1] += xv.y * wv.y; acc[1][2] += xv.y * wv.z; acc[1][3] += xv.y * wv.w;
        acc[2][0] += xv.z * wv.x; acc[2][1] += xv.z * wv.y; acc[2][2] += xv.z * wv.z; acc[2][3] += xv.z * wv.w;
        acc[3][0] += xv.w * wv.x; acc[3][1] += xv.w * wv.y; acc[3][2] += xv.w * wv.z; acc[3][3] += xv.w * wv.w;
    }

    float lb0 = s_lb[(oq << 2) + 0], lb1 = s_lb[(oq << 2) + 1];
    float lb2 = s_lb[(oq << 2) + 2], lb3 = s_lb[(oq << 2) + 3];
#pragma unroll
    for (int dn = 0; dn < 4; dn++) {
        int n = n0 + (nq << 2) + dn;
        float ci = cinv[n];
        float4 ag = *reinterpret_cast<const float4*>(&agg[(size_t)n * 64 + (oq << 2)]);
        float v0 = acc[dn][0] + lb0 + ag.x * ci;
        float v1 = acc[dn][1] + lb1 + ag.y * ci;
        float v2 = acc[dn][2] + lb2 + ag.z * ci;
        float v3 = acc[dn][3] + lb3 + ag.w * ci;
        float ss = v0 * v0 + v1 * v1 + v2 * v2 + v3 * v3;
        ss += __shfl_down_sync(0xffffffffu, ss, 8, 16);
        ss += __shfl_down_sync(0xffffffffu, ss, 4, 16);
        ss += __shfl_down_sync(0xffffffffu, ss, 2, 16);
        ss += __shfl_down_sync(0xffffffffu, ss, 1, 16);
        ss = __shfl_sync(0xffffffffu, ss, 0, 16);
        float sc = 1.f / fmaxf(sqrtf(ss), EPS_NORM);
        float4 o4 = make_float4(fmaxf(v0 * sc, 0.f), fmaxf(v1 * sc, 0.f),
                                fmaxf(v2 * sc, 0.f), fmaxf(v3 * sc, 0.f));
        *reinterpret_cast<float4*>(&out[(size_t)n * 64 + (oq << 2)]) = o4;
    }
}

// ------- conv3 finalize: out5 = agg*cinv + lb + x2@rw ; norm (no relu) -------
__global__ __launch_bounds__(128) void fin3_kernel(const float* __restrict__ x2,
                                                   const float* __restrict__ agg8,
                                                   const float* __restrict__ cinv,
                                                   const float* __restrict__ rw,
                                                   const float* __restrict__ lb,
                                                   float* __restrict__ out) {
    __shared__ float s_rw[64 * 8];
    __shared__ float s_lb[8];
    int t = threadIdx.x;
    for (int idx = t; idx < 320; idx += 128) s_rw[(idx / 5) * 8 + (idx % 5)] = rw[idx];
    if (t < 5) s_lb[t] = lb[t];
    __syncthreads();
    int n = blockIdx.x * 128 + t;
    if (n >= N_NODES) return;

    float ci = cinv[n];
    const float4* av = reinterpret_cast<const float4*>(agg8 + (size_t)n * 8);
    float4 a0 = av[0], a1 = av[1];
    float4 vf = make_float4(s_lb[0] + a0.x * ci, s_lb[1] + a0.y * ci,
                            s_lb[2] + a0.z * ci, s_lb[3] + a0.w * ci);
    float v4 = s_lb[4] + a1.x * ci;

    const float4* xr = reinterpret_cast<const float4*>(x2 + (size_t)n * 64);
#pragma unroll
    for (int iq = 0; iq < 16; iq++) {
        float4 xv = xr[iq];
        float xs[4] = {xv.x, xv.y, xv.z, xv.w};
#pragma unroll
        for (int c = 0; c < 4; c++) {
            int i = iq * 4 + c;
            float4 w = *reinterpret_cast<const float4*>(&s_rw[i * 8]);
            float w4 = s_rw[i * 8 + 4];
            vf.x += xs[c] * w.x;
            vf.y += xs[c] * w.y;
            vf.z += xs[c] * w.z;
            vf.w += xs[c] * w.w;
            v4 += xs[c] * w4;
        }
    }
    float ss = vf.x * vf.x + vf.y * vf.y + vf.z * vf.z + vf.w * vf.w + v4 * v4;
    float sc = 1.f / fmaxf(sqrtf(ss), EPS_NORM);
    float* o = out + (size_t)n * 5;
    o[0] = vf.x * sc;
    o[1] = vf.y * sc;
    o[2] = vf.z * sc;
    o[3] = vf.w * sc;
    o[4] = v4 * sc;
}

// ---------------- host launcher ----------------
extern "C" void kernel_launch(void* const* d_in, const int* in_sizes, int n_in,
                              void* d_out, int out_size) {
    const float* h = (const float*)d_in[0];
    const int* ei = (const int*)d_in[1];
    const float* ew = (const float*)d_in[2];
    const float* gamma = (const float*)d_in[3];
    const float* beta = (const float*)d_in[4];
    const float* c1_pw = (const float*)d_in[5];
    const float* c1_pb = (const float*)d_in[6];
    const float* c1_lw = (const float*)d_in[7];
    const float* c1_lb = (const float*)d_in[8];
    const float* c1_rw = (const float*)d_in[9];
    const float* c2_pw = (const float*)d_in[10];
    const float* c2_pb = (const float*)d_in[11];
    const float* c2_lw = (const float*)d_in[12];
    const float* c2_lb = (const float*)d_in[13];
    const float* c2_rw = (const float*)d_in[14];
    const float* c3_pw = (const float*)d_in[15];
    const float* c3_pb = (const float*)d_in[16];
    const float* c3_lw = (const float*)d_in[17];
    const float* c3_lb = (const float*)d_in[18];
    const float* c3_rw = (const float*)d_in[19];
    float* out = (float*)d_out;

    const int* src = ei;
    const int* dst = ei + N_EDGES;

    float *x0, *x1, *x2, *agg, *agg8, *cinv, *part;
    __half* yh;
    cudaGetSymbolAddress((void**)&x0, g_x0);
    cudaGetSymbolAddress((void**)&x1, g_x1);
    cudaGetSymbolAddress((void**)&x2, g_x2);
    cudaGetSymbolAddress((void**)&yh, g_yh);
    cudaGetSymbolAddress((void**)&agg, g_agg);
    cudaGetSymbolAddress((void**)&agg8, g_agg8);
    cudaGetSymbolAddress((void**)&cinv, g_cinv);
    cudaGetSymbolAddress((void**)&part, g_part);

    // 1: BN partial stats (no memsets anywhere)
    bn_stats_kernel<<<148, 256>>>(h, part);
    // 2: BN apply + conv1 5x5 projection (fp16 y8); zeroes agg8
    bn_conv1_kernel<<<(N_NODES + 255) / 256, 256>>>(h, part, gamma, beta, c1_pw, c1_pb,
                                                    x0, yh, agg8);
    // 3: conv1 push-scatter (width 5 + cnt)
    scatter8_kernel<true><<<6250, 256>>>(src, dst, ew, yh, agg8);
    // 4: conv1 finalize
    fin1_kernel<<<(N_NODES + 127) / 128, 128>>>(x0, agg8, c1_lw, c1_lb, c1_rw, x1, cinv);
    // 5: conv2 projection (zeroes agg: 512 float4 per block)
    proj_lw_kernel<64><<<N_NODES / 32, 128>>>(x1, c2_pw, c2_pb, c2_lw, yh, agg, 512);
    // 6: conv2 push-scatter (CAPTURED BY NCU)
    scatter64_kernel<<<4096, 256>>>(src, dst, ew, yh, agg);
    // 7: conv2 finalize (zeroes agg8 for conv3)
    fin64_kernel<<<N_NODES / 32, 128>>>(x1, agg, cinv, c2_rw, c2_lb, x2, agg8);
    // 8: conv3 projection
    proj_lw_kernel<5><<<N_NODES / 32, 128>>>(x2, c3_pw, c3_pb, c3_lw, yh, nullptr, 0);
    // 9: conv3 push-scatter (width 5)
    scatter8_kernel<false><<<6250, 256>>>(src, dst, ew, yh, agg8);
    // 10: conv3 finalize
    fin3_kernel<<<(N_NODES + 127) / 128, 128>>>(x2, agg8, cinv, c3_rw, c3_lb, out);
}

// round 6
// speedup vs baseline: 1.3300x; 1.1418x over previous
#include <cuda_runtime.h>
#include <cuda_fp16.h>
#include <cstdint>
#include <math.h>

#define N_NODES 100000
#define N_EDGES 3200000
#define EPS_BN 1e-5f
#define EPS_NORM 1e-12f

// ---------------- device scratch (no allocation allowed) ----------------
__device__ __align__(16) float g_x0[N_NODES * 8];     // BN output (padded stride 8)
__device__ __align__(16) float g_x1[N_NODES * 64];    // conv1 output
__device__ __align__(16) float g_x2[N_NODES * 64];    // conv2 output
__device__ __align__(16) __half g_yh[N_NODES * 64];   // fp16 projected features (stride 64 or 8)
__device__ __align__(16) __half g_aggh[N_NODES * 64]; // conv2 accumulator (fp16 atomics)
__device__ __align__(32) float g_agg8[N_NODES * 8];   // conv1/conv3 accumulator (5 feats + cnt)
__device__ float g_cinv[N_NODES];                     // 1/max(cnt,1)
__device__ __align__(16) float g_part[148 * 16];      // BN per-block partials

// ---------------- vector reductions ----------------
__device__ __forceinline__ void red_add_v4(float* p, float4 v) {
    asm volatile("red.global.add.v4.f32 [%0], {%1,%2,%3,%4};"
                 :: "l"(p), "f"(v.x), "f"(v.y), "f"(v.z), "f"(v.w) : "memory");
}
__device__ __forceinline__ void red_add_v2(float* p, float a, float b) {
    asm volatile("red.global.add.v2.f32 [%0], {%1,%2};"
                 :: "l"(p), "f"(a), "f"(b) : "memory");
}
__device__ __forceinline__ void red_add_f32(float* p, float a) {
    asm volatile("red.global.add.f32 [%0], %1;"
                 :: "l"(p), "f"(a) : "memory");
}
__device__ __forceinline__ void red_add_v2_h2(__half* p, uint32_t a, uint32_t b) {
    asm volatile("red.global.add.noftz.v2.f16x2 [%0], {%1,%2};"
                 :: "l"(p), "r"(a), "r"(b) : "memory");
}

// ------- BatchNorm statistics: per-block partials (no pre-zeroing) -------
__global__ __launch_bounds__(256) void bn_stats_kernel(const float* __restrict__ h,
                                                       float* __restrict__ part) {
    float s[5] = {0, 0, 0, 0, 0}, q[5] = {0, 0, 0, 0, 0};
    int stride = gridDim.x * blockDim.x;
    for (int n = blockIdx.x * blockDim.x + threadIdx.x; n < N_NODES; n += stride) {
#pragma unroll
        for (int i = 0; i < 5; i++) {
            float v = h[n * 5 + i];
            s[i] += v;
            q[i] += v * v;
        }
    }
#pragma unroll
    for (int k = 16; k > 0; k >>= 1) {
#pragma unroll
        for (int i = 0; i < 5; i++) {
            s[i] += __shfl_down_sync(0xffffffffu, s[i], k);
            q[i] += __shfl_down_sync(0xffffffffu, q[i], k);
        }
    }
    __shared__ float sh[10];
    if (threadIdx.x < 10) sh[threadIdx.x] = 0.f;
    __syncthreads();
    if ((threadIdx.x & 31) == 0) {
#pragma unroll
        for (int i = 0; i < 5; i++) {
            atomicAdd(&sh[i], s[i]);
            atomicAdd(&sh[5 + i], q[i]);
        }
    }
    __syncthreads();
    if (threadIdx.x < 10) part[blockIdx.x * 16 + threadIdx.x] = sh[threadIdx.x];
}

// ------- BN apply + conv1 projection (5x5) -> fp16 y8 ; zero agg8 -------
__global__ __launch_bounds__(256) void bn_conv1_kernel(const float* __restrict__ h,
                                                       const float* __restrict__ part,
                                                       const float* __restrict__ gamma,
                                                       const float* __restrict__ beta,
                                                       const float* __restrict__ pw,
                                                       const float* __restrict__ pb,
                                                       float* __restrict__ x0p,
                                                       __half* __restrict__ y8,
                                                       float* __restrict__ agg8) {
    __shared__ float s_warp[8][10];
    __shared__ float s_stats[10];
    int t = threadIdx.x;
    int lane = t & 31, wid = t >> 5;
    {
        float v[10];
#pragma unroll
        for (int i = 0; i < 10; i++) v[i] = 0.f;
        if (t < 148) {
#pragma unroll
            for (int i = 0; i < 10; i++) v[i] = part[t * 16 + i];
        }
#pragma unroll
        for (int k = 16; k > 0; k >>= 1) {
#pragma unroll
            for (int i = 0; i < 10; i++) v[i] += __shfl_down_sync(0xffffffffu, v[i], k);
        }
        if (lane == 0) {
#pragma unroll
            for (int i = 0; i < 10; i++) s_warp[wid][i] = v[i];
        }
    }
    __syncthreads();
    if (t < 10) {
        float acc = 0.f;
#pragma unroll
        for (int w = 0; w < 8; w++) acc += s_warp[w][t];
        s_stats[t] = acc;
    }
    __syncthreads();

    int n = blockIdx.x * blockDim.x + t;
    if (n >= N_NODES) return;
    const float inv_n = 1.f / (float)N_NODES;
    float xr[5];
#pragma unroll
    for (int i = 0; i < 5; i++) {
        float mu = s_stats[i] * inv_n;
        float var = s_stats[5 + i] * inv_n - mu * mu;
        float sc = rsqrtf(var + EPS_BN) * gamma[i];
        xr[i] = (h[n * 5 + i] - mu) * sc + beta[i];
    }
    float4* x0v = reinterpret_cast<float4*>(x0p + (size_t)n * 8);
    x0v[0] = make_float4(xr[0], xr[1], xr[2], xr[3]);
    x0v[1] = make_float4(xr[4], 0.f, 0.f, 0.f);
    float xp[5];
#pragma unroll
    for (int k = 0; k < 5; k++) {
        float v = pb[k];
#pragma unroll
        for (int i = 0; i < 5; i++) v += xr[i] * pw[i * 5 + k];
        xp[k] = fmaxf(v, 0.f);
    }
    __half2 h0 = __floats2half2_rn(xp[0], xp[1]);
    __half2 h1 = __floats2half2_rn(xp[2], xp[3]);
    __half2 h2 = __floats2half2_rn(xp[4], 0.f);
    uint4 pack;
    pack.x = *reinterpret_cast<uint32_t*>(&h0);
    pack.y = *reinterpret_cast<uint32_t*>(&h1);
    pack.z = *reinterpret_cast<uint32_t*>(&h2);
    pack.w = 0u;
    *reinterpret_cast<uint4*>(y8 + (size_t)n * 8) = pack;
    float4* av = reinterpret_cast<float4*>(agg8 + (size_t)n * 8);
    float4 z = make_float4(0.f, 0.f, 0.f, 0.f);
    av[0] = z;
    av[1] = z;
}

// -------- width-8 push scatter (fp16 reads, fp32 atomics) --------
template <bool ADD_CNT>
__global__ void scatter8_kernel(const int* __restrict__ src,
                                const int* __restrict__ dst,
                                const float* __restrict__ ew,
                                const __half* __restrict__ y8,
                                float* __restrict__ agg8) {
    int stride = gridDim.x * blockDim.x;
    for (int e = blockIdx.x * blockDim.x + threadIdx.x; e < N_EDGES; e += stride) {
        int s = __ldg(&src[e]);
        int d = __ldg(&dst[e]);
        float w = __ldg(&ew[e]);
        uint4 raw = *reinterpret_cast<const uint4*>(y8 + (size_t)s * 8);
        float2 f0 = __half22float2(*reinterpret_cast<__half2*>(&raw.x));
        float2 f1 = __half22float2(*reinterpret_cast<__half2*>(&raw.y));
        float2 f2 = __half22float2(*reinterpret_cast<__half2*>(&raw.z));
        red_add_v4(agg8 + (size_t)d * 8,
                   make_float4(f0.x * w, f0.y * w, f1.x * w, f1.y * w));
        if (ADD_CNT)
            red_add_v2(agg8 + (size_t)d * 8 + 4, f2.x * w, 1.0f);
        else
            red_add_f32(agg8 + (size_t)d * 8 + 4, f2.x * w);
    }
}

// -------- width-64 push scatter: fp16 reads AND fp16 atomics --------
__global__ void scatter64_kernel(const int* __restrict__ src,
                                 const int* __restrict__ dst,
                                 const float* __restrict__ ew,
                                 const __half* __restrict__ y,
                                 __half* __restrict__ agg) {
    int lane = threadIdx.x & 31;
    int warp = (blockIdx.x * blockDim.x + threadIdx.x) >> 5;
    int nwarps = (gridDim.x * blockDim.x) >> 5;
    int half = lane >> 4;         // which edge of the pair
    int fq = (lane & 15) << 2;    // feature offset (4 halves)
    const int npairs = N_EDGES / 2;
    for (int p = warp; p < npairs; p += nwarps) {
        int e = 2 * p + half;
        int s = __ldg(&src[e]);
        int d = __ldg(&dst[e]);
        float w = __ldg(&ew[e]);
        uint2 raw = *reinterpret_cast<const uint2*>(y + (size_t)s * 64 + fq);
        float2 f0 = __half22float2(*reinterpret_cast<__half2*>(&raw.x));
        float2 f1 = __half22float2(*reinterpret_cast<__half2*>(&raw.y));
        __half2 h0 = __floats2half2_rn(f0.x * w, f0.y * w);
        __half2 h1 = __floats2half2_rn(f1.x * w, f1.y * w);
        red_add_v2_h2(agg + (size_t)d * 64 + fq,
                      *reinterpret_cast<uint32_t*>(&h0),
                      *reinterpret_cast<uint32_t*>(&h1));
    }
}

// ------- conv1 finalize (fin64-style): 32 nodes/block, K=10 GEMM -------
// out64 = [mean5; x0] @ [lw; rw] + lb ; L2-norm ; relu
__global__ __launch_bounds__(128) void fin1_kernel(const float* __restrict__ x0p,
                                                   const float* __restrict__ agg8,
                                                   const float* __restrict__ lw,
                                                   const float* __restrict__ lb,
                                                   const float* __restrict__ rw,
                                                   float* __restrict__ x1,
                                                   float* __restrict__ cinv_out) {
    __shared__ float s_w[10 * 64];
    __shared__ float s_x[10][40];
    __shared__ float s_lb[64];
    __shared__ float s_ci[32];
    const int t = threadIdx.x;
    const int n0 = blockIdx.x * 32;

    for (int idx = t; idx < 640; idx += 128)
        s_w[idx] = (idx < 320) ? lw[idx] : rw[idx - 320];
    if (t < 64) s_lb[t] = lb[t];
    if (t < 32) {
        float c = agg8[(size_t)(n0 + t) * 8 + 5];
        float ci = 1.f / fmaxf(c, 1.f);
        s_ci[t] = ci;
        cinv_out[n0 + t] = ci;
    }
    __syncthreads();
    for (int idx = t; idx < 320; idx += 128) {
        int i = idx >> 5, nd = idx & 31;
        s_x[i][nd] = (i < 5) ? agg8[(size_t)(n0 + nd) * 8 + i] * s_ci[nd]
                             : x0p[(size_t)(n0 + nd) * 8 + (i - 5)];
    }
    __syncthreads();

    const int oq = t & 15, nq = t >> 4;
    float acc[4][4];
#pragma unroll
    for (int a = 0; a < 4; a++)
#pragma unroll
        for (int b = 0; b < 4; b++) acc[a][b] = 0.f;
#pragma unroll
    for (int i = 0; i < 10; i++) {
        float4 xv = *reinterpret_cast<const float4*>(&s_x[i][nq << 2]);
        float4 wv = *reinterpret_cast<const float4*>(&s_w[(i << 6) + (oq << 2)]);
        acc[0][0] += xv.x * wv.x; acc[0][1] += xv.x * wv.y; acc[0][2] += xv.x * wv.z; acc[0][3] += xv.x * wv.w;
        acc[1][0] += xv.y * wv.x; acc[1][1] += xv.y * wv.y; acc[1][2] += xv.y * wv.z; acc[1][3] += xv.y * wv.w;
        acc[2][0] += xv.z * wv.x; acc[2][1] += xv.z * wv.y; acc[2][2] += xv.z * wv.z; acc[2][3] += xv.z * wv.w;
        acc[3][0] += xv.w * wv.x; acc[3][1] += xv.w * wv.y; acc[3][2] += xv.w * wv.z; acc[3][3] += xv.w * wv.w;
    }

    float lb0 = s_lb[(oq << 2) + 0], lb1 = s_lb[(oq << 2) + 1];
    float lb2 = s_lb[(oq << 2) + 2], lb3 = s_lb[(oq << 2) + 3];
#pragma unroll
    for (int dn = 0; dn < 4; dn++) {
        int n = n0 + (nq << 2) + dn;
        float v0 = acc[dn][0] + lb0;
        float v1 = acc[dn][1] + lb1;
        float v2 = acc[dn][2] + lb2;
        float v3 = acc[dn][3] + lb3;
        float ss = v0 * v0 + v1 * v1 + v2 * v2 + v3 * v3;
        ss += __shfl_down_sync(0xffffffffu, ss, 8, 16);
        ss += __shfl_down_sync(0xffffffffu, ss, 4, 16);
        ss += __shfl_down_sync(0xffffffffu, ss, 2, 16);
        ss += __shfl_down_sync(0xffffffffu, ss, 1, 16);
        ss = __shfl_sync(0xffffffffu, ss, 0, 16);
        float sc = 1.f / fmaxf(sqrtf(ss), EPS_NORM);
        float4 o4 = make_float4(fmaxf(v0 * sc, 0.f), fmaxf(v1 * sc, 0.f),
                                fmaxf(v2 * sc, 0.f), fmaxf(v3 * sc, 0.f));
        *reinterpret_cast<float4*>(&x1[(size_t)n * 64 + (oq << 2)]) = o4;
    }
}

// -------- y(half) = relu(x@pw + pb) @ lw  (64 -> 64 -> OUT2) --------
// optionally zeroes a per-block slice of an accumulator (for next scatter)
template <int OUT2>
__global__ __launch_bounds__(128) void proj_lw_kernel(const float* __restrict__ x,
                                                      const float* __restrict__ pw,
                                                      const float* __restrict__ pb,
                                                      const float* __restrict__ lw,
                                                      __half* __restrict__ y,
                                                      void* __restrict__ zero_base,
                                                      int zero_f4_per_blk) {
    constexpr int OUTP = (OUT2 == 64) ? 64 : 8;
    constexpr int YS = (OUT2 == 64) ? 64 : 8;
    constexpr int NPB = 32;
    constexpr int XS = 36;
    __shared__ float s_w[64 * 64];
    __shared__ float s_x[64 * XS];
    __shared__ float s_xp[64 * XS];
    __shared__ float s_pb[64];
    const int t = threadIdx.x;
    const int n0 = blockIdx.x * NPB;

    if (zero_base) {
        float4 z = make_float4(0.f, 0.f, 0.f, 0.f);
        float4* zb = reinterpret_cast<float4*>(zero_base) + (size_t)blockIdx.x * zero_f4_per_blk;
        for (int i = t; i < zero_f4_per_blk; i += 128) zb[i] = z;
    }

    for (int i4 = t; i4 < 1024; i4 += 128)
        reinterpret_cast<float4*>(s_w)[i4] = reinterpret_cast<const float4*>(pw)[i4];
    if (t < 64) s_pb[t] = pb[t];
    for (int idx = t; idx < NPB * 64; idx += 128) {
        int n = idx >> 6, i = idx & 63;
        s_x[i * XS + n] = x[(size_t)(n0 + n) * 64 + i];
    }
    __syncthreads();

    const int oq = t & 15, nq = t >> 4;
    float acc[4][4];
#pragma unroll
    for (int a = 0; a < 4; a++)
#pragma unroll
        for (int b = 0; b < 4; b++) acc[a][b] = 0.f;

#pragma unroll 8
    for (int i = 0; i < 64; i++) {
        float4 xv = *reinterpret_cast<const float4*>(&s_x[i * XS + (nq << 2)]);
        float4 wv = *reinterpret_cast<const float4*>(&s_w[(i << 6) + (oq << 2)]);
        acc[0][0] += xv.x * wv.x; acc[0][1] += xv.x * wv.y; acc[0][2] += xv.x * wv.z; acc[0][3] += xv.x * wv.w;
        acc[1][0] += xv.y * wv.x; acc[1][1] += xv.y * wv.y; acc[1][2] += xv.y * wv.z; acc[1][3] += xv.y * wv.w;
        acc[2][0] += xv.z * wv.x; acc[2][1] += xv.z * wv.y; acc[2][2] += xv.z * wv.z; acc[2][3] += xv.z * wv.w;
        acc[3][0] += xv.w * wv.x; acc[3][1] += xv.w * wv.y; acc[3][2] += xv.w * wv.z; acc[3][3] += xv.w * wv.w;
    }
#pragma unroll
    for (int dk = 0; dk < 4; dk++) {
        float b = s_pb[(oq << 2) + dk];
#pragma unroll
        for (int dn = 0; dn < 4; dn++) {
            s_xp[((oq << 2) + dk) * XS + (nq << 2) + dn] = fmaxf(acc[dn][dk] + b, 0.f);
        }
    }
    __syncthreads();

    if (OUT2 == 64) {
        for (int i4 = t; i4 < 1024; i4 += 128)
            reinterpret_cast<float4*>(s_w)[i4] = reinterpret_cast<const float4*>(lw)[i4];
    } else {
        for (int idx = t; idx < 64 * 8; idx += 128) s_w[idx] = 0.f;
        __syncthreads();
        for (int idx = t; idx < 64 * 5; idx += 128) s_w[(idx / 5) * 8 + (idx % 5)] = lw[idx];
    }
    __syncthreads();

    constexpr int OQ2 = OUTP / 4;
    if (oq < OQ2) {
        float a2[4][4];
#pragma unroll
        for (int a = 0; a < 4; a++)
#pragma unroll
            for (int b = 0; b < 4; b++) a2[a][b] = 0.f;
#pragma unroll 8
        for (int i = 0; i < 64; i++) {
            float4 xv = *reinterpret_cast<const float4*>(&s_xp[i * XS + (nq << 2)]);
            float4 wv = *reinterpret_cast<const float4*>(&s_w[i * OUTP + (oq << 2)]);
            a2[0][0] += xv.x * wv.x; a2[0][1] += xv.x * wv.y; a2[0][2] += xv.x * wv.z; a2[0][3] += xv.x * wv.w;
            a2[1][0] += xv.y * wv.x; a2[1][1] += xv.y * wv.y; a2[1][2] += xv.y * wv.z; a2[1][3] += xv.y * wv.w;
            a2[2][0] += xv.z * wv.x; a2[2][1] += xv.z * wv.y; a2[2][2] += xv.z * wv.z; a2[2][3] += xv.z * wv.w;
            a2[3][0] += xv.w * wv.x; a2[3][1] += xv.w * wv.y; a2[3][2] += xv.w * wv.z; a2[3][3] += xv.w * wv.w;
        }
#pragma unroll
        for (int dn = 0; dn < 4; dn++) {
            __half2 h0 = __floats2half2_rn(a2[dn][0], a2[dn][1]);
            __half2 h1 = __floats2half2_rn(a2[dn][2], a2[dn][3]);
            uint2 pack;
            pack.x = *reinterpret_cast<uint32_t*>(&h0);
            pack.y = *reinterpret_cast<uint32_t*>(&h1);
            *reinterpret_cast<uint2*>(y + (size_t)(n0 + (nq << 2) + dn) * YS + (oq << 2)) = pack;
        }
    }
}

// ------- conv2 finalize: out = agg(half)*cinv + lb + x@rw ; norm ; relu ; zero agg8 -------
__global__ __launch_bounds__(128) void fin64_kernel(const float* __restrict__ x,
                                                    const __half* __restrict__ agg,
                                                    const float* __restrict__ cinv,
                                                    const float* __restrict__ rw,
                                                    const float* __restrict__ lb,
                                                    float* __restrict__ out,
                                                    float* __restrict__ agg8z) {
    constexpr int NPB = 32;
    constexpr int XS = 36;
    __shared__ float s_w[64 * 64];
    __shared__ float s_x[64 * XS];
    __shared__ float s_lb[64];
    const int t = threadIdx.x;
    const int n0 = blockIdx.x * NPB;

    if (t < 64) {
        float4 z = make_float4(0.f, 0.f, 0.f, 0.f);
        reinterpret_cast<float4*>(agg8z + (size_t)n0 * 8)[t] = z;
    }

    for (int i4 = t; i4 < 1024; i4 += 128)
        reinterpret_cast<float4*>(s_w)[i4] = reinterpret_cast<const float4*>(rw)[i4];
    if (t < 64) s_lb[t] = lb[t];
    for (int idx = t; idx < NPB * 64; idx += 128) {
        int n = idx >> 6, i = idx & 63;
        s_x[i * XS + n] = x[(size_t)(n0 + n) * 64 + i];
    }
    __syncthreads();

    const int oq = t & 15, nq = t >> 4;
    float acc[4][4];
#pragma unroll
    for (int a = 0; a < 4; a++)
#pragma unroll
        for (int b = 0; b < 4; b++) acc[a][b] = 0.f;
#pragma unroll 8
    for (int i = 0; i < 64; i++) {
        float4 xv = *reinterpret_cast<const float4*>(&s_x[i * XS + (nq << 2)]);
        float4 wv = *reinterpret_cast<const float4*>(&s_w[(i << 6) + (oq << 2)]);
        acc[0][0] += xv.x * wv.x; acc[0][1] += xv.x * wv.y; acc[0][2] += xv.x * wv.z; acc[0][3] += xv.x * wv.w;
        acc[1][0] += xv.y * wv.x; acc[1][1] += xv.y * wv.y; acc[1][2] += xv.y * wv.z; acc[1][3] += xv.y * wv.w;
        acc[2][0] += xv.z * wv.x; acc[2][1] += xv.z * wv.y; acc[2][2] += xv.z * wv.z; acc[2][3] += xv.z * wv.w;
        acc[3][0] += xv.w * wv.x; acc[3][1] += xv.w * wv.y; acc[3][2] += xv.w * wv.z; acc[3][3] += xv.w * wv.w;
    }

    float lb0 = s_lb[(oq << 2) + 0], lb1 = s_lb[(oq << 2) + 1];
    float lb2 = s_lb[(oq << 2) + 2], lb3 = s_lb[(oq << 2) + 3];
#pragma unroll
    for (int dn = 0; dn < 4; dn++) {
        int n = n0 + (nq << 2) + dn;
        float ci = cinv[n];
        uint2 raw = *reinterpret_cast<const uint2*>(agg + (size_t)n * 64 + (oq << 2));
        float2 g0 = __half22float2(*reinterpret_cast<__half2*>(&raw.x));
        float2 g1 = __half22float2(*reinterpret_cast<__half2*>(&raw.y));
        float v0 = acc[dn][0] + lb0 + g0.x * ci;
        float v1 = acc[dn][1] + lb1 + g0.y * ci;
        float v2 = acc[dn][2] + lb2 + g1.x * ci;
        float v3 = acc[dn][3] + lb3 + g1.y * ci;
        float ss = v0 * v0 + v1 * v1 + v2 * v2 + v3 * v3;
        ss += __shfl_down_sync(0xffffffffu, ss, 8, 16);
        ss += __shfl_down_sync(0xffffffffu, ss, 4, 16);
        ss += __shfl_down_sync(0xffffffffu, ss, 2, 16);
        ss += __shfl_down_sync(0xffffffffu, ss, 1, 16);
        ss = __shfl_sync(0xffffffffu, ss, 0, 16);
        float sc = 1.f / fmaxf(sqrtf(ss), EPS_NORM);
        float4 o4 = make_float4(fmaxf(v0 * sc, 0.f), fmaxf(v1 * sc, 0.f),
                                fmaxf(v2 * sc, 0.f), fmaxf(v3 * sc, 0.f));
        *reinterpret_cast<float4*>(&out[(size_t)n * 64 + (oq << 2)]) = o4;
    }
}

// ------- conv3 finalize: out5 = agg*cinv + lb + x2@rw ; norm (no relu) -------
__global__ __launch_bounds__(128) void fin3_kernel(const float* __restrict__ x2,
                                                   const float* __restrict__ agg8,
                                                   const float* __restrict__ cinv,
                                                   const float* __restrict__ rw,
                                                   const float* __restrict__ lb,
                                                   float* __restrict__ out) {
    __shared__ float s_rw[64 * 8];
    __shared__ float s_lb[8];
    int t = threadIdx.x;
    for (int idx = t; idx < 320; idx += 128) s_rw[(idx / 5) * 8 + (idx % 5)] = rw[idx];
    if (t < 5) s_lb[t] = lb[t];
    __syncthreads();
    int n = blockIdx.x * 128 + t;
    if (n >= N_NODES) return;

    float ci = cinv[n];
    const float4* av = reinterpret_cast<const float4*>(agg8 + (size_t)n * 8);
    float4 a0 = av[0], a1 = av[1];
    float4 vf = make_float4(s_lb[0] + a0.x * ci, s_lb[1] + a0.y * ci,
                            s_lb[2] + a0.z * ci, s_lb[3] + a0.w * ci);
    float v4 = s_lb[4] + a1.x * ci;

    const float4* xr = reinterpret_cast<const float4*>(x2 + (size_t)n * 64);
#pragma unroll
    for (int iq = 0; iq < 16; iq++) {
        float4 xv = xr[iq];
        float xs[4] = {xv.x, xv.y, xv.z, xv.w};
#pragma unroll
        for (int c = 0; c < 4; c++) {
            int i = iq * 4 + c;
            float4 w = *reinterpret_cast<const float4*>(&s_rw[i * 8]);
            float w4 = s_rw[i * 8 + 4];
            vf.x += xs[c] * w.x;
            vf.y += xs[c] * w.y;
            vf.z += xs[c] * w.z;
            vf.w += xs[c] * w.w;
            v4 += xs[c] * w4;
        }
    }
    float ss = vf.x * vf.x + vf.y * vf.y + vf.z * vf.z + vf.w * vf.w + v4 * v4;
    float sc = 1.f / fmaxf(sqrtf(ss), EPS_NORM);
    float* o = out + (size_t)n * 5;
    o[0] = vf.x * sc;
    o[1] = vf.y * sc;
    o[2] = vf.z * sc;
    o[3] = vf.w * sc;
    o[4] = v4 * sc;
}

// ---------------- host launcher ----------------
extern "C" void kernel_launch(void* const* d_in, const int* in_sizes, int n_in,
                              void* d_out, int out_size) {
    const float* h = (const float*)d_in[0];
    const int* ei = (const int*)d_in[1];
    const float* ew = (const float*)d_in[2];
    const float* gamma = (const float*)d_in[3];
    const float* beta = (const float*)d_in[4];
    const float* c1_pw = (const float*)d_in[5];
    const float* c1_pb = (const float*)d_in[6];
    const float* c1_lw = (const float*)d_in[7];
    const float* c1_lb = (const float*)d_in[8];
    const float* c1_rw = (const float*)d_in[9];
    const float* c2_pw = (const float*)d_in[10];
    const float* c2_pb = (const float*)d_in[11];
    const float* c2_lw = (const float*)d_in[12];
    const float* c2_lb = (const float*)d_in[13];
    const float* c2_rw = (const float*)d_in[14];
    const float* c3_pw = (const float*)d_in[15];
    const float* c3_pb = (const float*)d_in[16];
    const float* c3_lw = (const float*)d_in[17];
    const float* c3_lb = (const float*)d_in[18];
    const float* c3_rw = (const float*)d_in[19];
    float* out = (float*)d_out;

    const int* src = ei;
    const int* dst = ei + N_EDGES;

    float *x0, *x1, *x2, *agg8, *cinv, *part;
    __half *yh, *aggh;
    cudaGetSymbolAddress((void**)&x0, g_x0);
    cudaGetSymbolAddress((void**)&x1, g_x1);
    cudaGetSymbolAddress((void**)&x2, g_x2);
    cudaGetSymbolAddress((void**)&yh, g_yh);
    cudaGetSymbolAddress((void**)&aggh, g_aggh);
    cudaGetSymbolAddress((void**)&agg8, g_agg8);
    cudaGetSymbolAddress((void**)&cinv, g_cinv);
    cudaGetSymbolAddress((void**)&part, g_part);

    // 1: BN partial stats
    bn_stats_kernel<<<148, 256>>>(h, part);
    // 2: BN apply + conv1 5x5 projection (fp16 y8); zeroes agg8
    bn_conv1_kernel<<<(N_NODES + 255) / 256, 256>>>(h, part, gamma, beta, c1_pw, c1_pb,
                                                    x0, yh, agg8);
    // 3: conv1 push-scatter (width 5 + cnt, fp32 atomics)
    scatter8_kernel<true><<<6250, 256>>>(src, dst, ew, yh, agg8);
    // 4: conv1 finalize (K=10 GEMM style)
    fin1_kernel<<<N_NODES / 32, 128>>>(x0, agg8, c1_lw, c1_lb, c1_rw, x1, cinv);
    // 5: conv2 projection (zeroes aggh: 32 nodes * 64 halves = 256 float4/block)
    proj_lw_kernel<64><<<N_NODES / 32, 128>>>(x1, c2_pw, c2_pb, c2_lw, yh, aggh, 256);
    // 6: conv2 push-scatter (fp16 atomics)
    scatter64_kernel<<<4096, 256>>>(src, dst, ew, yh, aggh);
    // 7: conv2 finalize (zeroes agg8 for conv3)
    fin64_kernel<<<N_NODES / 32, 128>>>(x1, aggh, cinv, c2_rw, c2_lb, x2, agg8);
    // 8: conv3 projection
    proj_lw_kernel<5><<<N_NODES / 32, 128>>>(x2, c3_pw, c3_pb, c3_lw, yh, nullptr, 0);
    // 9: conv3 push-scatter (width 5, fp32 atomics)
    scatter8_kernel<false><<<6250, 256>>>(src, dst, ew, yh, agg8);
    // 10: conv3 finalize
    fin3_kernel<<<(N_NODES + 127) / 128, 128>>>(x2, agg8, cinv, c3_rw, c3_lb, out);
}